// round 1
// baseline (speedup 1.0000x reference)
#include <cuda_runtime.h>
#include <math.h>

#define NROWS 8192
#define DIN   512
#define HID   1024
#define EMBD  64
#define NCON  62
#define NCLS  16
#define MARGINF 0.01f
#define OUT_OFF (NROWS * DIN)

// ---------------- scratch (device globals; no allocation allowed) ----------------
__device__ float  g_data[NROWS * DIN];
__device__ int    g_lbl[NROWS];
__device__ float  g_h1[NROWS * HID];
__device__ float  g_emb[NROWS * EMBD];
__device__ float  g_h2[NROWS * HID];
__device__ float  g_sq[NROWS];
__device__ int    g_counts[NCLS];
__device__ int    g_off[NCLS];
__device__ int    g_cur[NCLS];
__device__ int    g_idx[NROWS];
__device__ double g_S[NCLS * NCON];
__device__ double g_Q[NCLS];
__device__ double g_cdiff;

// ---------------- init: zero all accumulators (must happen every replay) --------
__global__ void k_init() {
    int t = threadIdx.x;
    if (t < NCLS) { g_counts[t] = 0; g_Q[t] = 0.0; }
    if (t == 0) g_cdiff = 0.0;
    for (int i = t; i < NCLS * NCON; i += blockDim.x) g_S[i] = 0.0;
}

// ---------------- prep: split x into labels + contiguous data, count classes ----
__global__ void k_prep(const float* __restrict__ x) {
    const int total = NROWS * (DIN + 1);
    for (int e = blockIdx.x * blockDim.x + threadIdx.x; e < total;
         e += gridDim.x * blockDim.x) {
        int i = e / (DIN + 1);
        int j = e - i * (DIN + 1);
        float v = x[e];
        if (j == 0) {
            int c = (int)v;
            g_lbl[i] = c;
            atomicAdd(&g_counts[c], 1);
        } else {
            g_data[i * DIN + (j - 1)] = v;
        }
    }
}

__global__ void k_offsets() {
    if (threadIdx.x == 0) {
        int s = 0;
        for (int c = 0; c < NCLS; c++) { g_off[c] = s; g_cur[c] = s; s += g_counts[c]; }
    }
}

__global__ void k_scatter() {
    int i = blockIdx.x * blockDim.x + threadIdx.x;
    if (i < NROWS) {
        int c = g_lbl[i];
        int p = atomicAdd(&g_cur[c], 1);
        g_idx[p] = i;
    }
}

// ---------------- tiled SGEMM: C[M,N] = act(A[M,K] @ B[K,N] + bias) -------------
// BM=BN=64, BK=16, 256 threads, 4x4 register tile. All dims divide tiles exactly.
__global__ __launch_bounds__(256)
void k_sgemm(const float* __restrict__ A, const float* __restrict__ B,
             const float* __restrict__ bias, float* __restrict__ C,
             int M, int N, int K, int act) {
    __shared__ float As[16][68];  // transposed, padded (272B rows keep f4 align)
    __shared__ float Bs[16][64];

    const int tid  = threadIdx.x;
    const int bm   = blockIdx.y * 64;
    const int bn   = blockIdx.x * 64;
    const int arow = tid >> 2;          // 0..63
    const int acol = (tid & 3) * 4;     // 0,4,8,12
    const int brow = tid >> 4;          // 0..15
    const int bcol = (tid & 15) * 4;    // 0..60
    const int ty   = tid >> 4;          // 0..15
    const int tx   = tid & 15;          // 0..15

    float acc[4][4] = {};

    for (int k0 = 0; k0 < K; k0 += 16) {
        float4 av = *(const float4*)&A[(bm + arow) * K + k0 + acol];
        float4 bv = *(const float4*)&B[(k0 + brow) * N + bn + bcol];
        __syncthreads();
        As[acol + 0][arow] = av.x;
        As[acol + 1][arow] = av.y;
        As[acol + 2][arow] = av.z;
        As[acol + 3][arow] = av.w;
        *(float4*)&Bs[brow][bcol] = bv;
        __syncthreads();
#pragma unroll
        for (int k = 0; k < 16; k++) {
            float4 a = *(const float4*)&As[k][ty * 4];
            float4 b = *(const float4*)&Bs[k][tx * 4];
            float ar[4] = {a.x, a.y, a.z, a.w};
            float br[4] = {b.x, b.y, b.z, b.w};
#pragma unroll
            for (int i = 0; i < 4; i++)
#pragma unroll
                for (int j = 0; j < 4; j++) acc[i][j] += ar[i] * br[j];
        }
    }

    float bb[4];
#pragma unroll
    for (int j = 0; j < 4; j++) bb[j] = bias[bn + tx * 4 + j];
#pragma unroll
    for (int i = 0; i < 4; i++) {
        int row = bm + ty * 4 + i;
        float4 r;
        float v0 = acc[i][0] + bb[0];
        float v1 = acc[i][1] + bb[1];
        float v2 = acc[i][2] + bb[2];
        float v3 = acc[i][3] + bb[3];
        if (act) { v0 = tanhf(v0); v1 = tanhf(v1); v2 = tanhf(v2); v3 = tanhf(v3); }
        r.x = v0; r.y = v1; r.z = v2; r.w = v3;
        *(float4*)&C[row * N + bn + tx * 4] = r;
    }
}

// ---------------- per-row squared norm of conserved dims + per-class Q ----------
__global__ void k_sq() {
    int row  = blockIdx.x * 8 + (threadIdx.x >> 5);
    int lane = threadIdx.x & 31;
    float s = 0.f;
    for (int d = lane; d < NCON; d += 32) {
        float v = g_emb[row * EMBD + 2 + d];
        s += v * v;
    }
#pragma unroll
    for (int o = 16; o; o >>= 1) s += __shfl_xor_sync(0xffffffff, s, o);
    if (lane == 0) {
        g_sq[row] = s;
        atomicAdd(&g_Q[g_lbl[row]], (double)s);
    }
}

// ---------------- per-class vector sums S_c (double) ----------------------------
__global__ void k_S() {
    int c = blockIdx.x;
    int d = threadIdx.x;
    if (d >= NCON) return;
    int n = g_counts[c], off = g_off[c];
    double a0 = 0, a1 = 0, a2 = 0, a3 = 0;
    int r = 0;
    for (; r + 4 <= n; r += 4) {
        a0 += (double)g_emb[g_idx[off + r + 0] * EMBD + 2 + d];
        a1 += (double)g_emb[g_idx[off + r + 1] * EMBD + 2 + d];
        a2 += (double)g_emb[g_idx[off + r + 2] * EMBD + 2 + d];
        a3 += (double)g_emb[g_idx[off + r + 3] * EMBD + 2 + d];
    }
    for (; r < n; r++) a0 += (double)g_emb[g_idx[off + r] * EMBD + 2 + d];
    g_S[c * NCON + d] = a0 + a1 + a2 + a3;
}

// ---------------- same-class pairwise hinge (C_diff numerator) ------------------
// Block = 64x64 pair tile within one class; grid.y = class, grid.x strides tiles.
__global__ __launch_bounds__(256)
void k_pairs() {
    const int c   = blockIdx.y;
    const int n   = g_counts[c];
    const int off = g_off[c];
    const int nt  = (n + 63) >> 6;
    const int tot = nt * nt;

    __shared__ float  smA[NCON][68];
    __shared__ float  smB[NCON][68];
    __shared__ float  sqA[64], sqB[64];
    __shared__ double red[256];

    const int tid = threadIdx.x;
    const int ty  = tid >> 4, tx = tid & 15;
    double acc = 0.0;

    for (int t = blockIdx.x; t < tot; t += gridDim.x) {
        int TI = t / nt, TJ = t - TI * nt;
        int i0 = TI * 64, j0 = TJ * 64;
        __syncthreads();
        for (int e = tid; e < NCON * 64; e += 256) {
            int d = e >> 6, r = e & 63;
            int ri = i0 + r, rj = j0 + r;
            smA[d][r] = (ri < n) ? g_emb[g_idx[off + ri] * EMBD + 2 + d] : 0.f;
            smB[d][r] = (rj < n) ? g_emb[g_idx[off + rj] * EMBD + 2 + d] : 0.f;
        }
        if (tid < 64) {
            sqA[tid] = (i0 + tid < n) ? g_sq[g_idx[off + i0 + tid]] : 1e30f;
            sqB[tid] = (j0 + tid < n) ? g_sq[g_idx[off + j0 + tid]] : 1e30f;
        }
        __syncthreads();
        float dot[4][4] = {};
#pragma unroll
        for (int k = 0; k < NCON; k++) {
            float a[4], b[4];
#pragma unroll
            for (int i = 0; i < 4; i++) a[i] = smA[k][ty * 4 + i];
#pragma unroll
            for (int j = 0; j < 4; j++) b[j] = smB[k][tx * 4 + j];
#pragma unroll
            for (int i = 0; i < 4; i++)
#pragma unroll
                for (int j = 0; j < 4; j++) dot[i][j] += a[i] * b[j];
        }
#pragma unroll
        for (int i = 0; i < 4; i++) {
            float si = sqA[ty * 4 + i];
#pragma unroll
            for (int j = 0; j < 4; j++) {
                float df = si + sqB[tx * 4 + j] - 2.f * dot[i][j];
                float dm = fmaxf(df, 0.f) * (1.0f / 62.0f);
                float cc = fmaxf(0.f, MARGINF - dm);
                acc += (double)cc;
            }
        }
    }
    red[tid] = acc;
    __syncthreads();
    for (int o = 128; o; o >>= 1) {
        if (tid < o) red[tid] += red[tid + o];
        __syncthreads();
    }
    if (tid == 0 && red[0] != 0.0) atomicAdd(&g_cdiff, red[0]);
}

// ---------------- finalize: closed-form C_sim + C_diff scalars ------------------
__global__ void k_final(float* __restrict__ out) {
    __shared__ double shA[64], shB[64];
    int d = threadIdx.x;  // 64 threads
    double sgd = 0.0, s2c = 0.0;
    if (d < NCON) {
        for (int c = 0; c < NCLS; c++) {
            double v = g_S[c * NCON + d];
            sgd += v;
            s2c += v * v;
        }
    }
    shA[d] = sgd * sgd;  // contributes to ||sum S||^2
    shB[d] = s2c;        // contributes to sum_c ||S_c||^2
    __syncthreads();
    if (d == 0) {
        double S2g = 0.0, S2c = 0.0;
        for (int k = 0; k < 64; k++) { S2g += shA[k]; S2c += shB[k]; }
        double T = 0.0, sumn2 = 0.0, snq = 0.0;
        for (int c = 0; c < NCLS; c++) {
            double nc = (double)g_counts[c];
            T     += g_Q[c];
            sumn2 += nc * nc;
            snq   += 2.0 * nc * g_Q[c];
        }
        double Nd     = (double)NROWS;
        double n_diff = Nd * Nd - sumn2;
        double sum_all  = 2.0 * Nd * T - 2.0 * S2g;  // sum over ALL pairs of ||ci-cj||^2
        double sum_same = snq - 2.0 * S2c;           // sum over same-class pairs
        double C_sim  = (sum_all - sum_same) / 62.0 / (n_diff + 1.0);
        double C_diff = g_cdiff / (Nd * Nd - n_diff + 1.0);
        out[OUT_OFF + 0] = (float)C_sim;
        out[OUT_OFF + 1] = (float)C_diff;
    }
}

// ---------------- launch --------------------------------------------------------
extern "C" void kernel_launch(void* const* d_in, const int* in_sizes, int n_in,
                              void* d_out, int out_size) {
    const float* x  = (const float*)d_in[0];
    const float* W1 = (const float*)d_in[1];
    const float* b1 = (const float*)d_in[2];
    const float* W2 = (const float*)d_in[3];
    const float* b2 = (const float*)d_in[4];
    const float* W3 = (const float*)d_in[5];
    const float* b3 = (const float*)d_in[6];
    const float* W4 = (const float*)d_in[7];
    const float* b4 = (const float*)d_in[8];
    float* out = (float*)d_out;

    float *p_data, *p_h1, *p_emb, *p_h2;
    cudaGetSymbolAddress((void**)&p_data, g_data);
    cudaGetSymbolAddress((void**)&p_h1,   g_h1);
    cudaGetSymbolAddress((void**)&p_emb,  g_emb);
    cudaGetSymbolAddress((void**)&p_h2,   g_h2);

    k_init<<<1, 1024>>>();
    k_prep<<<8192, 256>>>(x);
    k_offsets<<<1, 32>>>();
    k_scatter<<<32, 256>>>();

    // h1 = tanh(data @ W1 + b1)        [8192,1024]
    k_sgemm<<<dim3(HID / 64, NROWS / 64), 256>>>(p_data, W1, b1, p_h1,
                                                 NROWS, HID, DIN, 1);
    // emb = h1 @ W2 + b2               [8192,64]
    k_sgemm<<<dim3(EMBD / 64, NROWS / 64), 256>>>(p_h1, W2, b2, p_emb,
                                                  NROWS, EMBD, HID, 0);
    k_sq<<<NROWS / 8, 256>>>();
    k_S<<<NCLS, 64>>>();
    // h2 = tanh(emb @ W3 + b3)         [8192,1024]
    k_sgemm<<<dim3(HID / 64, NROWS / 64), 256>>>(p_emb, W3, b3, p_h2,
                                                 NROWS, HID, EMBD, 1);
    // decoded = h2 @ W4 + b4 -> d_out  [8192,512]
    k_sgemm<<<dim3(DIN / 64, NROWS / 64), 256>>>(p_h2, W4, b4, out,
                                                 NROWS, DIN, HID, 0);
    k_pairs<<<dim3(64, NCLS), 256>>>();
    k_final<<<1, 64>>>(out);
}

// round 3
// speedup vs baseline: 1.5774x; 1.5774x over previous
#include <cuda_runtime.h>
#include <cuda_bf16.h>
#include <cstdint>
#include <math.h>

#define NROWS 8192
#define DIN   512
#define HID   1024
#define EMBD  64
#define NCON  62
#define NCLS  16
#define MARGINF 0.01f
#define OUT_OFF (NROWS * DIN)

// ======================= helpers ================================================
__device__ __forceinline__ uint32_t smem_u32(const void* p) {
    uint32_t a;
    asm("{ .reg .u64 t; cvta.to.shared.u64 t, %1; cvt.u32.u64 %0, t; }" : "=r"(a) : "l"(p));
    return a;
}
__device__ __forceinline__ void ld16(uint32_t s, const void* g) {
    asm volatile("cp.async.cg.shared.global [%0], [%1], 16;" :: "r"(s), "l"(g));
}
__device__ __forceinline__ void ldsm4(uint32_t* r, uint32_t addr) {
    asm volatile("ldmatrix.sync.aligned.m8n8.x4.shared.b16 {%0,%1,%2,%3}, [%4];"
        : "=r"(r[0]), "=r"(r[1]), "=r"(r[2]), "=r"(r[3]) : "r"(addr));
}
__device__ __forceinline__ void mma16816(float* c, const uint32_t* a, const uint32_t* b) {
    asm volatile("mma.sync.aligned.m16n8k16.row.col.f32.bf16.bf16.f32 "
        "{%0,%1,%2,%3}, {%4,%5,%6,%7}, {%8,%9}, {%0,%1,%2,%3};"
        : "+f"(c[0]), "+f"(c[1]), "+f"(c[2]), "+f"(c[3])
        : "r"(a[0]), "r"(a[1]), "r"(a[2]), "r"(a[3]), "r"(b[0]), "r"(b[1]));
}

// ======================= scratch (device globals) ===============================
__device__ __nv_bfloat16 g_data_h[NROWS * DIN],  g_data_l[NROWS * DIN];
__device__ __nv_bfloat16 g_h1_h[NROWS * HID],    g_h1_l[NROWS * HID];
__device__ __nv_bfloat16 g_emb_h[NROWS * EMBD],  g_emb_l[NROWS * EMBD];
__device__ __nv_bfloat16 g_h2_h[NROWS * HID],    g_h2_l[NROWS * HID];
__device__ __nv_bfloat16 g_w1_h[HID * DIN],  g_w1_l[HID * DIN];    // [N,K]
__device__ __nv_bfloat16 g_w2_h[EMBD * HID], g_w2_l[EMBD * HID];
__device__ __nv_bfloat16 g_w3_h[HID * EMBD], g_w3_l[HID * EMBD];
__device__ __nv_bfloat16 g_w4_h[DIN * HID],  g_w4_l[DIN * HID];
__device__ float  g_emb[NROWS * EMBD];
__device__ int    g_lbl[NROWS];
__device__ float  g_sq[NROWS];
__device__ int    g_counts[NCLS], g_off[NCLS], g_cur[NCLS], g_idx[NROWS];
__device__ double g_S[NCLS * NCON];
__device__ double g_Q[NCLS];
__device__ double g_cdiff;

// ======================= small kernels ==========================================
__global__ void k_init() {
    int t = threadIdx.x;
    if (t < NCLS) { g_counts[t] = 0; g_Q[t] = 0.0; }
    if (t == 0) g_cdiff = 0.0;
    for (int i = t; i < NCLS * NCON; i += blockDim.x) g_S[i] = 0.0;
}

__global__ void k_prep(const float* __restrict__ x) {
    const int total = NROWS * (DIN + 1);
    for (int e = blockIdx.x * blockDim.x + threadIdx.x; e < total;
         e += gridDim.x * blockDim.x) {
        int i = e / (DIN + 1);
        int j = e - i * (DIN + 1);
        float v = x[e];
        if (j == 0) {
            int c = (int)v;
            g_lbl[i] = c;
            atomicAdd(&g_counts[c], 1);
        } else {
            __nv_bfloat16 h = __float2bfloat16(v);
            float lo = v - __bfloat162float(h);
            int idx = i * DIN + (j - 1);
            g_data_h[idx] = h;
            g_data_l[idx] = __float2bfloat16(lo);
        }
    }
}

// transpose + split W[K,N] -> [N,K] bf16 hi/lo
__global__ void k_wt(const float* __restrict__ W, __nv_bfloat16* __restrict__ th,
                     __nv_bfloat16* __restrict__ tl, int K, int N) {
    int e = blockIdx.x * blockDim.x + threadIdx.x;
    if (e < K * N) {
        int k = e / N, n = e - k * N;
        float v = W[e];
        __nv_bfloat16 h = __float2bfloat16(v);
        float lo = v - __bfloat162float(h);
        th[n * K + k] = h;
        tl[n * K + k] = __float2bfloat16(lo);
    }
}

__global__ void k_offsets() {
    if (threadIdx.x == 0) {
        int s = 0;
        for (int c = 0; c < NCLS; c++) { g_off[c] = s; g_cur[c] = s; s += g_counts[c]; }
    }
}

__global__ void k_scatter() {
    int i = blockIdx.x * blockDim.x + threadIdx.x;
    if (i < NROWS) {
        int c = g_lbl[i];
        int p = atomicAdd(&g_cur[c], 1);
        g_idx[p] = i;
    }
}

// ======================= mma.sync bf16-split GEMM ===============================
// C[M,N] = act(A[M,K] @ Bt[N,K]^T + bias); A,Bt given as bf16 hi/lo pairs.
// 3 products accumulate in fp32: Ah*Bh + Ah*Bl + Al*Bh.
// CTA: 256 thr (8 warps, 4x2), tile 128 x NT, K chunks of 32, cp.async 2-stage.
template<int NT>
__global__ __launch_bounds__(256)
void k_gemm_mma(const __nv_bfloat16* __restrict__ Ah, const __nv_bfloat16* __restrict__ Al,
                const __nv_bfloat16* __restrict__ Bh, const __nv_bfloat16* __restrict__ Bl,
                const float* __restrict__ bias, float* __restrict__ f32out,
                __nv_bfloat16* __restrict__ oh, __nv_bfloat16* __restrict__ ol,
                int K, int N, int act) {
    constexpr int WN   = NT / 2;        // warp N tile
    constexpr int NW8  = WN / 8;        // n8 frags per warp
    constexpr int NJ   = WN / 16;       // n16 ldsm groups
    constexpr int STRB = 80;            // smem row stride bytes (32 bf16 + 8 pad)
    constexpr int ABY  = 128 * STRB;
    constexpr int BBY  = NT * STRB;
    constexpr int OFF_AL = ABY;
    constexpr int OFF_BH = 2 * ABY;
    constexpr int OFF_BL = 2 * ABY + BBY;
    constexpr int BUFSZ  = 2 * ABY + 2 * BBY;

    extern __shared__ __align__(16) char smem[];
    const uint32_t sbase = smem_u32(smem);

    const int tid = threadIdx.x;
    const int wid = tid >> 5, lane = tid & 31;
    const int wr = wid >> 1, wc = wid & 1;
    const int bm = blockIdx.y * 128, bn = blockIdx.x * NT;

    float acc[2][NW8][4];
#pragma unroll
    for (int a = 0; a < 2; a++)
#pragma unroll
        for (int b = 0; b < NW8; b++)
#pragma unroll
            for (int c = 0; c < 4; c++) acc[a][b][c] = 0.f;

    const int nch = K >> 5;

    auto load_chunk = [&](int buf, int kc) {
        const int k0 = kc << 5;
        const uint32_t sb = sbase + buf * BUFSZ;
        for (int u = tid; u < 128 * 4; u += 256) {
            int r = u >> 2, s = u & 3;
            size_t go = (size_t)(bm + r) * K + k0 + s * 8;
            uint32_t so = (uint32_t)(r * STRB + s * 16);
            ld16(sb + so, Ah + go);
            ld16(sb + OFF_AL + so, Al + go);
        }
        for (int u = tid; u < NT * 4; u += 256) {
            int r = u >> 2, s = u & 3;
            size_t go = (size_t)(bn + r) * K + k0 + s * 8;
            uint32_t so = (uint32_t)(r * STRB + s * 16);
            ld16(sb + OFF_BH + so, Bh + go);
            ld16(sb + OFF_BL + so, Bl + go);
        }
        asm volatile("cp.async.commit_group;" ::: "memory");
    };

    load_chunk(0, 0);
    for (int kc = 0; kc < nch; kc++) {
        if (kc + 1 < nch) {
            load_chunk((kc + 1) & 1, kc + 1);
            asm volatile("cp.async.wait_group 1;" ::: "memory");
        } else {
            asm volatile("cp.async.wait_group 0;" ::: "memory");
        }
        __syncthreads();

        const uint32_t sb = sbase + (kc & 1) * BUFSZ;
#pragma unroll
        for (int ks = 0; ks < 2; ks++) {
            uint32_t ah[2][4], alr[2][4], bh[NW8][2], blr[NW8][2];
#pragma unroll
            for (int mi = 0; mi < 2; mi++) {
                uint32_t ar = wr * 32 + mi * 16 + (lane & 15);
                uint32_t ac = ks * 16 + (lane >> 4) * 8;
                uint32_t ad = sb + ar * STRB + ac * 2;
                ldsm4(ah[mi], ad);
                ldsm4(alr[mi], ad + OFF_AL);
            }
#pragma unroll
            for (int nj = 0; nj < NJ; nj++) {
                uint32_t br = wc * WN + nj * 16 + ((lane >> 4) << 3) + (lane & 7);
                uint32_t bc = ks * 16 + ((lane >> 3) & 1) * 8;
                uint32_t bd = sb + OFF_BH + br * STRB + bc * 2;
                uint32_t t[4];
                ldsm4(t, bd);
                bh[2 * nj][0] = t[0]; bh[2 * nj][1] = t[1];
                bh[2 * nj + 1][0] = t[2]; bh[2 * nj + 1][1] = t[3];
                ldsm4(t, bd + (OFF_BL - OFF_BH));
                blr[2 * nj][0] = t[0]; blr[2 * nj][1] = t[1];
                blr[2 * nj + 1][0] = t[2]; blr[2 * nj + 1][1] = t[3];
            }
#pragma unroll
            for (int mi = 0; mi < 2; mi++)
#pragma unroll
                for (int ni = 0; ni < NW8; ni++) {
                    mma16816(acc[mi][ni], ah[mi],  bh[ni]);
                    mma16816(acc[mi][ni], ah[mi],  blr[ni]);
                    mma16816(acc[mi][ni], alr[mi], bh[ni]);
                }
        }
        __syncthreads();
    }

    // epilogue: bias + optional tanh, direct stores (float2 / bf16x2 pairs)
    const int g = lane >> 2, i2 = (lane & 3) * 2;
#pragma unroll
    for (int mi = 0; mi < 2; mi++) {
#pragma unroll
        for (int ni = 0; ni < NW8; ni++) {
            int col = bn + wc * WN + ni * 8 + i2;
            float b0 = bias[col], b1 = bias[col + 1];
#pragma unroll
            for (int h = 0; h < 2; h++) {
                int row = bm + wr * 32 + mi * 16 + g + h * 8;
                float v0 = acc[mi][ni][2 * h] + b0;
                float v1 = acc[mi][ni][2 * h + 1] + b1;
                if (act) { v0 = tanhf(v0); v1 = tanhf(v1); }
                size_t oi = (size_t)row * N + col;
                if (f32out) *(float2*)(f32out + oi) = make_float2(v0, v1);
                if (oh) {
                    __nv_bfloat16 h0 = __float2bfloat16(v0);
                    __nv_bfloat16 h1 = __float2bfloat16(v1);
                    float l0 = v0 - __bfloat162float(h0);
                    float l1 = v1 - __bfloat162float(h1);
                    *(__nv_bfloat162*)(oh + oi) = __halves2bfloat162(h0, h1);
                    *(__nv_bfloat162*)(ol + oi) =
                        __halves2bfloat162(__float2bfloat16(l0), __float2bfloat16(l1));
                }
            }
        }
    }
}

// ======================= embedding stats ========================================
__global__ void k_sq() {
    int row  = blockIdx.x * 8 + (threadIdx.x >> 5);
    int lane = threadIdx.x & 31;
    float s = 0.f;
    for (int d = lane; d < NCON; d += 32) {
        float v = g_emb[row * EMBD + 2 + d];
        s += v * v;
    }
#pragma unroll
    for (int o = 16; o; o >>= 1) s += __shfl_xor_sync(0xffffffff, s, o);
    if (lane == 0) {
        g_sq[row] = s;
        atomicAdd(&g_Q[g_lbl[row]], (double)s);
    }
}

__global__ void k_S() {
    int c = blockIdx.x;
    int d = threadIdx.x;
    if (d >= NCON) return;
    int n = g_counts[c], off = g_off[c];
    double a0 = 0, a1 = 0, a2 = 0, a3 = 0;
    int r = 0;
    for (; r + 4 <= n; r += 4) {
        a0 += (double)g_emb[g_idx[off + r + 0] * EMBD + 2 + d];
        a1 += (double)g_emb[g_idx[off + r + 1] * EMBD + 2 + d];
        a2 += (double)g_emb[g_idx[off + r + 2] * EMBD + 2 + d];
        a3 += (double)g_emb[g_idx[off + r + 3] * EMBD + 2 + d];
    }
    for (; r < n; r++) a0 += (double)g_emb[g_idx[off + r] * EMBD + 2 + d];
    g_S[c * NCON + d] = a0 + a1 + a2 + a3;
}

// ======================= same-class pairwise hinge ==============================
__global__ __launch_bounds__(256)
void k_pairs() {
    const int c   = blockIdx.y;
    const int n   = g_counts[c];
    const int off = g_off[c];
    const int nt  = (n + 63) >> 6;
    const int tot = nt * nt;

    __shared__ float  smA[NCON][68];
    __shared__ float  smB[NCON][68];
    __shared__ float  sqA[64], sqB[64];
    __shared__ double red[256];

    const int tid = threadIdx.x;
    const int ty  = tid >> 4, tx = tid & 15;
    double acc = 0.0;

    for (int t = blockIdx.x; t < tot; t += gridDim.x) {
        int TI = t / nt, TJ = t - TI * nt;
        int i0 = TI * 64, j0 = TJ * 64;
        __syncthreads();
        for (int e = tid; e < NCON * 64; e += 256) {
            int d = e >> 6, r = e & 63;
            int ri = i0 + r, rj = j0 + r;
            smA[d][r] = (ri < n) ? g_emb[g_idx[off + ri] * EMBD + 2 + d] : 0.f;
            smB[d][r] = (rj < n) ? g_emb[g_idx[off + rj] * EMBD + 2 + d] : 0.f;
        }
        if (tid < 64) {
            sqA[tid] = (i0 + tid < n) ? g_sq[g_idx[off + i0 + tid]] : 1e30f;
            sqB[tid] = (j0 + tid < n) ? g_sq[g_idx[off + j0 + tid]] : 1e30f;
        }
        __syncthreads();
        float dot[4][4] = {};
#pragma unroll
        for (int k = 0; k < NCON; k++) {
            float a[4], b[4];
#pragma unroll
            for (int i = 0; i < 4; i++) a[i] = smA[k][ty * 4 + i];
#pragma unroll
            for (int j = 0; j < 4; j++) b[j] = smB[k][tx * 4 + j];
#pragma unroll
            for (int i = 0; i < 4; i++)
#pragma unroll
                for (int j = 0; j < 4; j++) dot[i][j] += a[i] * b[j];
        }
#pragma unroll
        for (int i = 0; i < 4; i++) {
            float si = sqA[ty * 4 + i];
#pragma unroll
            for (int j = 0; j < 4; j++) {
                float df = si + sqB[tx * 4 + j] - 2.f * dot[i][j];
                float dm = fmaxf(df, 0.f) * (1.0f / 62.0f);
                float cc = fmaxf(0.f, MARGINF - dm);
                acc += (double)cc;
            }
        }
    }
    red[tid] = acc;
    __syncthreads();
    for (int o = 128; o; o >>= 1) {
        if (tid < o) red[tid] += red[tid + o];
        __syncthreads();
    }
    if (tid == 0 && red[0] != 0.0) atomicAdd(&g_cdiff, red[0]);
}

// ======================= finalize scalars =======================================
__global__ void k_final(float* __restrict__ out) {
    __shared__ double shA[64], shB[64];
    int d = threadIdx.x;
    double sgd = 0.0, s2c = 0.0;
    if (d < NCON) {
        for (int c = 0; c < NCLS; c++) {
            double v = g_S[c * NCON + d];
            sgd += v;
            s2c += v * v;
        }
    }
    shA[d] = sgd * sgd;
    shB[d] = s2c;
    __syncthreads();
    if (d == 0) {
        double S2g = 0.0, S2c = 0.0;
        for (int k = 0; k < 64; k++) { S2g += shA[k]; S2c += shB[k]; }
        double T = 0.0, sumn2 = 0.0, snq = 0.0;
        for (int c = 0; c < NCLS; c++) {
            double nc = (double)g_counts[c];
            T     += g_Q[c];
            sumn2 += nc * nc;
            snq   += 2.0 * nc * g_Q[c];
        }
        double Nd     = (double)NROWS;
        double n_diff = Nd * Nd - sumn2;
        double sum_all  = 2.0 * Nd * T - 2.0 * S2g;
        double sum_same = snq - 2.0 * S2c;
        double C_sim  = (sum_all - sum_same) / 62.0 / (n_diff + 1.0);
        double C_diff = g_cdiff / (Nd * Nd - n_diff + 1.0);
        out[OUT_OFF + 0] = (float)C_sim;
        out[OUT_OFF + 1] = (float)C_diff;
    }
}

// ======================= launch =================================================
extern "C" void kernel_launch(void* const* d_in, const int* in_sizes, int n_in,
                              void* d_out, int out_size) {
    const float* x  = (const float*)d_in[0];
    const float* W1 = (const float*)d_in[1];
    const float* b1 = (const float*)d_in[2];
    const float* W2 = (const float*)d_in[3];
    const float* b2 = (const float*)d_in[4];
    const float* W3 = (const float*)d_in[5];
    const float* b3 = (const float*)d_in[6];
    const float* W4 = (const float*)d_in[7];
    const float* b4 = (const float*)d_in[8];
    float* out = (float*)d_out;

    cudaFuncSetAttribute(k_gemm_mma<128>, cudaFuncAttributeMaxDynamicSharedMemorySize, 81920);
    cudaFuncSetAttribute(k_gemm_mma<64>,  cudaFuncAttributeMaxDynamicSharedMemorySize, 61440);

    __nv_bfloat16 *dh, *dl, *h1h, *h1l, *eh, *el, *h2h, *h2l;
    __nv_bfloat16 *w1h, *w1l, *w2h, *w2l, *w3h, *w3l, *w4h, *w4l;
    float* pemb;
    cudaGetSymbolAddress((void**)&dh,  g_data_h); cudaGetSymbolAddress((void**)&dl,  g_data_l);
    cudaGetSymbolAddress((void**)&h1h, g_h1_h);   cudaGetSymbolAddress((void**)&h1l, g_h1_l);
    cudaGetSymbolAddress((void**)&eh,  g_emb_h);  cudaGetSymbolAddress((void**)&el,  g_emb_l);
    cudaGetSymbolAddress((void**)&h2h, g_h2_h);   cudaGetSymbolAddress((void**)&h2l, g_h2_l);
    cudaGetSymbolAddress((void**)&w1h, g_w1_h);   cudaGetSymbolAddress((void**)&w1l, g_w1_l);
    cudaGetSymbolAddress((void**)&w2h, g_w2_h);   cudaGetSymbolAddress((void**)&w2l, g_w2_l);
    cudaGetSymbolAddress((void**)&w3h, g_w3_h);   cudaGetSymbolAddress((void**)&w3l, g_w3_l);
    cudaGetSymbolAddress((void**)&w4h, g_w4_h);   cudaGetSymbolAddress((void**)&w4l, g_w4_l);
    cudaGetSymbolAddress((void**)&pemb, g_emb);

    k_init<<<1, 1024>>>();
    k_prep<<<4096, 256>>>(x);
    k_wt<<<(DIN * HID + 255) / 256, 256>>>(W1, w1h, w1l, DIN, HID);
    k_wt<<<(HID * EMBD + 255) / 256, 256>>>(W2, w2h, w2l, HID, EMBD);
    k_wt<<<(EMBD * HID + 255) / 256, 256>>>(W3, w3h, w3l, EMBD, HID);
    k_wt<<<(HID * DIN + 255) / 256, 256>>>(W4, w4h, w4l, HID, DIN);
    k_offsets<<<1, 32>>>();
    k_scatter<<<32, 256>>>();

    // L1: h1 = tanh(data @ W1 + b1)        [8192,1024], K=512
    k_gemm_mma<128><<<dim3(HID / 128, NROWS / 128), 256, 81920>>>(
        dh, dl, w1h, w1l, b1, nullptr, h1h, h1l, DIN, HID, 1);
    // L2: emb = h1 @ W2 + b2               [8192,64], K=1024
    k_gemm_mma<64><<<dim3(1, NROWS / 128), 256, 61440>>>(
        h1h, h1l, w2h, w2l, b2, pemb, eh, el, HID, EMBD, 0);
    k_sq<<<NROWS / 8, 256>>>();
    k_S<<<NCLS, 64>>>();
    // L3: h2 = tanh(emb @ W3 + b3)         [8192,1024], K=64
    k_gemm_mma<128><<<dim3(HID / 128, NROWS / 128), 256, 81920>>>(
        eh, el, w3h, w3l, b3, nullptr, h2h, h2l, EMBD, HID, 1);
    // L4: decoded = h2 @ W4 + b4 -> d_out  [8192,512], K=1024
    k_gemm_mma<128><<<dim3(DIN / 128, NROWS / 128), 256, 81920>>>(
        h2h, h2l, w4h, w4l, b4, out, nullptr, nullptr, HID, DIN, 0);

    k_pairs<<<dim3(64, NCLS), 256>>>();
    k_final<<<1, 64>>>(out);
}

// round 4
// speedup vs baseline: 1.8618x; 1.1803x over previous
#include <cuda_runtime.h>
#include <cuda_bf16.h>
#include <cstdint>
#include <math.h>

#define NROWS 8192
#define DIN   512
#define HID   1024
#define EMBD  64
#define NCON  62
#define NCLS  16
#define MARGINF 0.01f
#define OUT_OFF (NROWS * DIN)

// ======================= helpers ================================================
__device__ __forceinline__ void ld16(uint32_t s, const void* g) {
    asm volatile("cp.async.cg.shared.global [%0], [%1], 16;" :: "r"(s), "l"(g));
}
__device__ __forceinline__ uint32_t smem_u32(const void* p) {
    uint32_t a;
    asm("{ .reg .u64 t; cvta.to.shared.u64 t, %1; cvt.u32.u64 %0, t; }" : "=r"(a) : "l"(p));
    return a;
}
__device__ __forceinline__ void ldsm4(uint32_t* r, uint32_t addr) {
    asm volatile("ldmatrix.sync.aligned.m8n8.x4.shared.b16 {%0,%1,%2,%3}, [%4];"
        : "=r"(r[0]), "=r"(r[1]), "=r"(r[2]), "=r"(r[3]) : "r"(addr));
}
__device__ __forceinline__ void mma16816(float* c, const uint32_t* a, const uint32_t* b) {
    asm volatile("mma.sync.aligned.m16n8k16.row.col.f32.bf16.bf16.f32 "
        "{%0,%1,%2,%3}, {%4,%5,%6,%7}, {%8,%9}, {%0,%1,%2,%3};"
        : "+f"(c[0]), "+f"(c[1]), "+f"(c[2]), "+f"(c[3])
        : "r"(a[0]), "r"(a[1]), "r"(a[2]), "r"(a[3]), "r"(b[0]), "r"(b[1]));
}

// ======================= scratch (device globals) ===============================
__device__ __nv_bfloat16 g_data_h[NROWS * DIN],  g_data_l[NROWS * DIN];
__device__ __nv_bfloat16 g_h1_h[NROWS * HID],    g_h1_l[NROWS * HID];
__device__ __nv_bfloat16 g_emb_h[NROWS * EMBD],  g_emb_l[NROWS * EMBD];
__device__ __nv_bfloat16 g_h2_h[NROWS * HID],    g_h2_l[NROWS * HID];
__device__ __nv_bfloat16 g_w1_h[HID * DIN],  g_w1_l[HID * DIN];    // [N,K]
__device__ __nv_bfloat16 g_w2_h[EMBD * HID], g_w2_l[EMBD * HID];
__device__ __nv_bfloat16 g_w3_h[HID * EMBD], g_w3_l[HID * EMBD];
__device__ __nv_bfloat16 g_w4_h[DIN * HID],  g_w4_l[DIN * HID];
__device__ float  g_emb[NROWS * EMBD];
__device__ int    g_lbl[NROWS];
__device__ float  g_sq[NROWS];
__device__ int    g_counts[NCLS], g_off[NCLS], g_cur[NCLS], g_idx[NROWS];
__device__ double g_S[NCLS * NCON];
__device__ double g_Q[NCLS];
__device__ double g_cdiff;

// ======================= small kernels ==========================================
__global__ void k_init() {
    int t = threadIdx.x;
    if (t < NCLS) { g_counts[t] = 0; g_Q[t] = 0.0; }
    if (t == 0) g_cdiff = 0.0;
    for (int i = t; i < NCLS * NCON; i += blockDim.x) g_S[i] = 0.0;
}

__global__ void k_prep(const float* __restrict__ x) {
    const int total = NROWS * (DIN + 1);
    for (int e = blockIdx.x * blockDim.x + threadIdx.x; e < total;
         e += gridDim.x * blockDim.x) {
        int i = e / (DIN + 1);
        int j = e - i * (DIN + 1);
        float v = x[e];
        if (j == 0) {
            int c = (int)v;
            g_lbl[i] = c;
            atomicAdd(&g_counts[c], 1);
        } else {
            __nv_bfloat16 h = __float2bfloat16(v);
            float lo = v - __bfloat162float(h);
            int idx = i * DIN + (j - 1);
            g_data_h[idx] = h;
            g_data_l[idx] = __float2bfloat16(lo);
        }
    }
}

// one kernel: transpose + split all four weight matrices W[K,N] -> [N,K] hi/lo
__global__ void k_wt_all(const float* __restrict__ W1, const float* __restrict__ W2,
                         const float* __restrict__ W3, const float* __restrict__ W4) {
    const int S1 = DIN * HID, S2 = HID * EMBD, S3 = EMBD * HID, S4 = HID * DIN;
    const int T1 = S1, T2 = T1 + S2, T3 = T2 + S3, T4 = T3 + S4;
    for (int e = blockIdx.x * blockDim.x + threadIdx.x; e < T4;
         e += gridDim.x * blockDim.x) {
        const float* W;
        __nv_bfloat16 *th, *tl;
        int le, K, N;
        if (e < T1)      { W = W1; th = g_w1_h; tl = g_w1_l; le = e;      K = DIN;  N = HID;  }
        else if (e < T2) { W = W2; th = g_w2_h; tl = g_w2_l; le = e - T1; K = HID;  N = EMBD; }
        else if (e < T3) { W = W3; th = g_w3_h; tl = g_w3_l; le = e - T2; K = EMBD; N = HID;  }
        else             { W = W4; th = g_w4_h; tl = g_w4_l; le = e - T3; K = HID;  N = DIN;  }
        int k = le / N, n = le - k * N;
        float v = W[le];
        __nv_bfloat16 h = __float2bfloat16(v);
        float lo = v - __bfloat162float(h);
        th[n * K + k] = h;
        tl[n * K + k] = __float2bfloat16(lo);
    }
}

__global__ void k_offsets() {
    if (threadIdx.x == 0) {
        int s = 0;
        for (int c = 0; c < NCLS; c++) { g_off[c] = s; g_cur[c] = s; s += g_counts[c]; }
    }
}

__global__ void k_scatter() {
    int i = blockIdx.x * blockDim.x + threadIdx.x;
    if (i < NROWS) {
        int c = g_lbl[i];
        int p = atomicAdd(&g_cur[c], 1);
        g_idx[p] = i;
    }
}

// ======================= mma.sync bf16-split GEMM ===============================
// C[M,N] = act(A[M,K] @ Bt[N,K]^T + bias); 3 products Ah*Bh + Ah*Bl + Al*Bh.
// CTA: 256 thr (8 warps, 4x2), tile 128 x NT, K chunks of 32, cp.async 2-stage,
// B fragments streamed through a 4-reg temp to keep regs <= 128 (2 CTAs/SM).
template<int NT>
__global__ __launch_bounds__(256, 2)
void k_gemm_mma(const __nv_bfloat16* __restrict__ Ah, const __nv_bfloat16* __restrict__ Al,
                const __nv_bfloat16* __restrict__ Bh, const __nv_bfloat16* __restrict__ Bl,
                const float* __restrict__ bias, float* __restrict__ f32out,
                __nv_bfloat16* __restrict__ oh, __nv_bfloat16* __restrict__ ol,
                int K, int N, int act) {
    constexpr int WN   = NT / 2;        // warp N tile
    constexpr int NW8  = WN / 8;        // n8 frags per warp
    constexpr int NJ   = WN / 16;       // n16 ldsm groups
    constexpr int STRB = 80;            // smem row stride bytes (32 bf16 + 8 pad)
    constexpr int ABY  = 128 * STRB;
    constexpr int BBY  = NT * STRB;
    constexpr int OFF_AL = ABY;
    constexpr int OFF_BH = 2 * ABY;
    constexpr int OFF_BL = 2 * ABY + BBY;
    constexpr int BUFSZ  = 2 * ABY + 2 * BBY;

    extern __shared__ __align__(16) char smem[];
    const uint32_t sbase = smem_u32(smem);

    const int tid = threadIdx.x;
    const int wid = tid >> 5, lane = tid & 31;
    const int wr = wid >> 1, wc = wid & 1;
    const int bm = blockIdx.y * 128, bn = blockIdx.x * NT;

    float acc[2][NW8][4];
#pragma unroll
    for (int a = 0; a < 2; a++)
#pragma unroll
        for (int b = 0; b < NW8; b++)
#pragma unroll
            for (int c = 0; c < 4; c++) acc[a][b][c] = 0.f;

    const int nch = K >> 5;

    auto load_chunk = [&](int buf, int kc) {
        const int k0 = kc << 5;
        const uint32_t sb = sbase + buf * BUFSZ;
        for (int u = tid; u < 128 * 4; u += 256) {
            int r = u >> 2, s = u & 3;
            size_t go = (size_t)(bm + r) * K + k0 + s * 8;
            uint32_t so = (uint32_t)(r * STRB + s * 16);
            ld16(sb + so, Ah + go);
            ld16(sb + OFF_AL + so, Al + go);
        }
        for (int u = tid; u < NT * 4; u += 256) {
            int r = u >> 2, s = u & 3;
            size_t go = (size_t)(bn + r) * K + k0 + s * 8;
            uint32_t so = (uint32_t)(r * STRB + s * 16);
            ld16(sb + OFF_BH + so, Bh + go);
            ld16(sb + OFF_BL + so, Bl + go);
        }
        asm volatile("cp.async.commit_group;" ::: "memory");
    };

    load_chunk(0, 0);
    for (int kc = 0; kc < nch; kc++) {
        if (kc + 1 < nch) {
            load_chunk((kc + 1) & 1, kc + 1);
            asm volatile("cp.async.wait_group 1;" ::: "memory");
        } else {
            asm volatile("cp.async.wait_group 0;" ::: "memory");
        }
        __syncthreads();

        const uint32_t sb = sbase + (kc & 1) * BUFSZ;
#pragma unroll
        for (int ks = 0; ks < 2; ks++) {
            // A hi/lo fragments stay live for the whole ks step (16 regs)
            uint32_t ah[2][4], alr[2][4];
#pragma unroll
            for (int mi = 0; mi < 2; mi++) {
                uint32_t ar = wr * 32 + mi * 16 + (lane & 15);
                uint32_t ac = ks * 16 + (lane >> 4) * 8;
                uint32_t ad = sb + ar * STRB + ac * 2;
                ldsm4(ah[mi], ad);
                ldsm4(alr[mi], ad + OFF_AL);
            }
            // B fragments streamed: 4-reg temp per ldsm, consumed immediately
            uint32_t br = wc * WN + ((lane >> 4) << 3) + (lane & 7);
            uint32_t bc = ks * 16 + ((lane >> 3) & 1) * 8;
#pragma unroll
            for (int nj = 0; nj < NJ; nj++) {
                uint32_t bd = sb + OFF_BH + (br + nj * 16) * STRB + bc * 2;
                uint32_t t[4];
                ldsm4(t, bd);
#pragma unroll
                for (int mi = 0; mi < 2; mi++) {
                    mma16816(acc[mi][2 * nj],     ah[mi],  t);
                    mma16816(acc[mi][2 * nj + 1], ah[mi],  t + 2);
                    mma16816(acc[mi][2 * nj],     alr[mi], t);
                    mma16816(acc[mi][2 * nj + 1], alr[mi], t + 2);
                }
                ldsm4(t, bd + (OFF_BL - OFF_BH));
#pragma unroll
                for (int mi = 0; mi < 2; mi++) {
                    mma16816(acc[mi][2 * nj],     ah[mi], t);
                    mma16816(acc[mi][2 * nj + 1], ah[mi], t + 2);
                }
            }
        }
        __syncthreads();
    }

    // epilogue: bias + optional tanh, direct stores (float2 / bf16x2 pairs)
    const int g = lane >> 2, i2 = (lane & 3) * 2;
#pragma unroll
    for (int mi = 0; mi < 2; mi++) {
#pragma unroll
        for (int ni = 0; ni < NW8; ni++) {
            int col = bn + wc * WN + ni * 8 + i2;
            float b0 = bias[col], b1 = bias[col + 1];
#pragma unroll
            for (int h = 0; h < 2; h++) {
                int row = bm + wr * 32 + mi * 16 + g + h * 8;
                float v0 = acc[mi][ni][2 * h] + b0;
                float v1 = acc[mi][ni][2 * h + 1] + b1;
                if (act) { v0 = tanhf(v0); v1 = tanhf(v1); }
                size_t oi = (size_t)row * N + col;
                if (f32out) *(float2*)(f32out + oi) = make_float2(v0, v1);
                if (oh) {
                    __nv_bfloat16 h0 = __float2bfloat16(v0);
                    __nv_bfloat16 h1 = __float2bfloat16(v1);
                    float l0 = v0 - __bfloat162float(h0);
                    float l1 = v1 - __bfloat162float(h1);
                    *(__nv_bfloat162*)(oh + oi) = __halves2bfloat162(h0, h1);
                    *(__nv_bfloat162*)(ol + oi) =
                        __halves2bfloat162(__float2bfloat16(l0), __float2bfloat16(l1));
                }
            }
        }
    }
}

// ======================= embedding stats ========================================
__global__ void k_sq() {
    int row  = blockIdx.x * 8 + (threadIdx.x >> 5);
    int lane = threadIdx.x & 31;
    float s = 0.f;
    for (int d = lane; d < NCON; d += 32) {
        float v = g_emb[row * EMBD + 2 + d];
        s += v * v;
    }
#pragma unroll
    for (int o = 16; o; o >>= 1) s += __shfl_xor_sync(0xffffffff, s, o);
    if (lane == 0) {
        g_sq[row] = s;
        atomicAdd(&g_Q[g_lbl[row]], (double)s);
    }
}

__global__ void k_S() {
    int c = blockIdx.x;
    int d = threadIdx.x;
    if (d >= NCON) return;
    int n = g_counts[c], off = g_off[c];
    double a0 = 0, a1 = 0, a2 = 0, a3 = 0;
    int r = 0;
    for (; r + 4 <= n; r += 4) {
        a0 += (double)g_emb[g_idx[off + r + 0] * EMBD + 2 + d];
        a1 += (double)g_emb[g_idx[off + r + 1] * EMBD + 2 + d];
        a2 += (double)g_emb[g_idx[off + r + 2] * EMBD + 2 + d];
        a3 += (double)g_emb[g_idx[off + r + 3] * EMBD + 2 + d];
    }
    for (; r < n; r++) a0 += (double)g_emb[g_idx[off + r] * EMBD + 2 + d];
    g_S[c * NCON + d] = a0 + a1 + a2 + a3;
}

// ======================= same-class pairwise hinge (triangular) =================
// Only TI<=TJ tiles; off-diagonal tiles weighted x2 (D symmetric).
__global__ __launch_bounds__(256)
void k_pairs() {
    const int c   = blockIdx.y;
    const int n   = g_counts[c];
    const int off = g_off[c];
    const int nt  = (n + 63) >> 6;
    const int tot = nt * (nt + 1) / 2;

    __shared__ float  smA[NCON][68];
    __shared__ float  smB[NCON][68];
    __shared__ float  sqA[64], sqB[64];
    __shared__ double red[256];

    const int tid = threadIdx.x;
    const int ty  = tid >> 4, tx = tid & 15;
    double acc = 0.0;

    for (int t = blockIdx.x; t < tot; t += gridDim.x) {
        int rem = t, TI = 0;
        while (rem >= nt - TI) { rem -= nt - TI; TI++; }
        int TJ = TI + rem;
        float w = (TI == TJ) ? 1.0f : 2.0f;
        int i0 = TI * 64, j0 = TJ * 64;
        __syncthreads();
        for (int e = tid; e < NCON * 64; e += 256) {
            int d = e >> 6, r = e & 63;
            int ri = i0 + r, rj = j0 + r;
            smA[d][r] = (ri < n) ? g_emb[g_idx[off + ri] * EMBD + 2 + d] : 0.f;
            smB[d][r] = (rj < n) ? g_emb[g_idx[off + rj] * EMBD + 2 + d] : 0.f;
        }
        if (tid < 64) {
            sqA[tid] = (i0 + tid < n) ? g_sq[g_idx[off + i0 + tid]] : 1e30f;
            sqB[tid] = (j0 + tid < n) ? g_sq[g_idx[off + j0 + tid]] : 1e30f;
        }
        __syncthreads();
        float dot[4][4] = {};
#pragma unroll
        for (int k = 0; k < NCON; k++) {
            float a[4], b[4];
#pragma unroll
            for (int i = 0; i < 4; i++) a[i] = smA[k][ty * 4 + i];
#pragma unroll
            for (int j = 0; j < 4; j++) b[j] = smB[k][tx * 4 + j];
#pragma unroll
            for (int i = 0; i < 4; i++)
#pragma unroll
                for (int j = 0; j < 4; j++) dot[i][j] += a[i] * b[j];
        }
        float ts = 0.f;
#pragma unroll
        for (int i = 0; i < 4; i++) {
            float si = sqA[ty * 4 + i];
#pragma unroll
            for (int j = 0; j < 4; j++) {
                float df = si + sqB[tx * 4 + j] - 2.f * dot[i][j];
                float dm = fmaxf(df, 0.f) * (1.0f / 62.0f);
                ts += fmaxf(0.f, MARGINF - dm);
            }
        }
        acc += (double)(w * ts);
    }
    red[tid] = acc;
    __syncthreads();
    for (int o = 128; o; o >>= 1) {
        if (tid < o) red[tid] += red[tid + o];
        __syncthreads();
    }
    if (tid == 0 && red[0] != 0.0) atomicAdd(&g_cdiff, red[0]);
}

// ======================= finalize scalars =======================================
__global__ void k_final(float* __restrict__ out) {
    __shared__ double shA[64], shB[64];
    int d = threadIdx.x;
    double sgd = 0.0, s2c = 0.0;
    if (d < NCON) {
        for (int c = 0; c < NCLS; c++) {
            double v = g_S[c * NCON + d];
            sgd += v;
            s2c += v * v;
        }
    }
    shA[d] = sgd * sgd;
    shB[d] = s2c;
    __syncthreads();
    if (d == 0) {
        double S2g = 0.0, S2c = 0.0;
        for (int k = 0; k < 64; k++) { S2g += shA[k]; S2c += shB[k]; }
        double T = 0.0, sumn2 = 0.0, snq = 0.0;
        for (int c = 0; c < NCLS; c++) {
            double nc = (double)g_counts[c];
            T     += g_Q[c];
            sumn2 += nc * nc;
            snq   += 2.0 * nc * g_Q[c];
        }
        double Nd     = (double)NROWS;
        double n_diff = Nd * Nd - sumn2;
        double sum_all  = 2.0 * Nd * T - 2.0 * S2g;
        double sum_same = snq - 2.0 * S2c;
        double C_sim  = (sum_all - sum_same) / 62.0 / (n_diff + 1.0);
        double C_diff = g_cdiff / (Nd * Nd - n_diff + 1.0);
        out[OUT_OFF + 0] = (float)C_sim;
        out[OUT_OFF + 1] = (float)C_diff;
    }
}

// ======================= launch =================================================
extern "C" void kernel_launch(void* const* d_in, const int* in_sizes, int n_in,
                              void* d_out, int out_size) {
    const float* x  = (const float*)d_in[0];
    const float* W1 = (const float*)d_in[1];
    const float* b1 = (const float*)d_in[2];
    const float* W2 = (const float*)d_in[3];
    const float* b2 = (const float*)d_in[4];
    const float* W3 = (const float*)d_in[5];
    const float* b3 = (const float*)d_in[6];
    const float* W4 = (const float*)d_in[7];
    const float* b4 = (const float*)d_in[8];
    float* out = (float*)d_out;

    cudaFuncSetAttribute(k_gemm_mma<128>, cudaFuncAttributeMaxDynamicSharedMemorySize, 81920);
    cudaFuncSetAttribute(k_gemm_mma<64>,  cudaFuncAttributeMaxDynamicSharedMemorySize, 61440);

    __nv_bfloat16 *dh, *dl, *h1h, *h1l, *eh, *el, *h2h, *h2l;
    __nv_bfloat16 *w1h, *w1l, *w2h, *w2l, *w3h, *w3l, *w4h, *w4l;
    float* pemb;
    cudaGetSymbolAddress((void**)&dh,  g_data_h); cudaGetSymbolAddress((void**)&dl,  g_data_l);
    cudaGetSymbolAddress((void**)&h1h, g_h1_h);   cudaGetSymbolAddress((void**)&h1l, g_h1_l);
    cudaGetSymbolAddress((void**)&eh,  g_emb_h);  cudaGetSymbolAddress((void**)&el,  g_emb_l);
    cudaGetSymbolAddress((void**)&h2h, g_h2_h);   cudaGetSymbolAddress((void**)&h2l, g_h2_l);
    cudaGetSymbolAddress((void**)&w1h, g_w1_h);   cudaGetSymbolAddress((void**)&w1l, g_w1_l);
    cudaGetSymbolAddress((void**)&w2h, g_w2_h);   cudaGetSymbolAddress((void**)&w2l, g_w2_l);
    cudaGetSymbolAddress((void**)&w3h, g_w3_h);   cudaGetSymbolAddress((void**)&w3l, g_w3_l);
    cudaGetSymbolAddress((void**)&w4h, g_w4_h);   cudaGetSymbolAddress((void**)&w4l, g_w4_l);
    cudaGetSymbolAddress((void**)&pemb, g_emb);

    k_init<<<1, 1024>>>();                                   // my #0
    k_prep<<<4096, 256>>>(x);                                // my #1
    k_wt_all<<<2304, 256>>>(W1, W2, W3, W4);                 // my #2

    // L1: h1 = tanh(data @ W1 + b1)  [8192,1024], K=512 --- my #3 (ncu target)
    k_gemm_mma<128><<<dim3(HID / 128, NROWS / 128), 256, 81920>>>(
        dh, dl, w1h, w1l, b1, nullptr, h1h, h1l, DIN, HID, 1);

    k_offsets<<<1, 32>>>();                                  // my #4
    k_scatter<<<32, 256>>>();                                // my #5

    // L2: emb = h1 @ W2 + b2         [8192,64], K=1024
    k_gemm_mma<64><<<dim3(1, NROWS / 128), 256, 61440>>>(
        h1h, h1l, w2h, w2l, b2, pemb, eh, el, HID, EMBD, 0);
    k_sq<<<NROWS / 8, 256>>>();
    k_S<<<NCLS, 64>>>();
    // L3: h2 = tanh(emb @ W3 + b3)   [8192,1024], K=64
    k_gemm_mma<128><<<dim3(HID / 128, NROWS / 128), 256, 81920>>>(
        eh, el, w3h, w3l, b3, nullptr, h2h, h2l, EMBD, HID, 1);
    // L4: decoded = h2 @ W4 + b4 -> d_out  [8192,512], K=1024
    k_gemm_mma<128><<<dim3(DIN / 128, NROWS / 128), 256, 81920>>>(
        h2h, h2l, w4h, w4l, b4, out, nullptr, nullptr, HID, DIN, 0);

    k_pairs<<<dim3(40, NCLS), 256>>>();
    k_final<<<1, 64>>>(out);
}

// round 5
// speedup vs baseline: 1.9222x; 1.0325x over previous
#include <cuda_runtime.h>
#include <cuda_bf16.h>
#include <cstdint>
#include <math.h>

#define NROWS 8192
#define DIN   512
#define HID   1024
#define EMBD  64
#define NCON  62
#define NCLS  16
#define MARGINF 0.01f
#define OUT_OFF (NROWS * DIN)

// ======================= helpers ================================================
__device__ __forceinline__ void ld16(uint32_t s, const void* g) {
    asm volatile("cp.async.cg.shared.global [%0], [%1], 16;" :: "r"(s), "l"(g));
}
__device__ __forceinline__ uint32_t smem_u32(const void* p) {
    uint32_t a;
    asm("{ .reg .u64 t; cvta.to.shared.u64 t, %1; cvt.u32.u64 %0, t; }" : "=r"(a) : "l"(p));
    return a;
}
__device__ __forceinline__ void ldsm4(uint32_t* r, uint32_t addr) {
    asm volatile("ldmatrix.sync.aligned.m8n8.x4.shared.b16 {%0,%1,%2,%3}, [%4];"
        : "=r"(r[0]), "=r"(r[1]), "=r"(r[2]), "=r"(r[3]) : "r"(addr));
}
__device__ __forceinline__ void mma16816(float* c, const uint32_t* a, const uint32_t* b) {
    asm volatile("mma.sync.aligned.m16n8k16.row.col.f32.bf16.bf16.f32 "
        "{%0,%1,%2,%3}, {%4,%5,%6,%7}, {%8,%9}, {%0,%1,%2,%3};"
        : "+f"(c[0]), "+f"(c[1]), "+f"(c[2]), "+f"(c[3])
        : "r"(a[0]), "r"(a[1]), "r"(a[2]), "r"(a[3]), "r"(b[0]), "r"(b[1]));
}

// ======================= scratch (device globals) ===============================
__device__ __nv_bfloat16 g_data_h[NROWS * DIN],  g_data_l[NROWS * DIN];
__device__ __nv_bfloat16 g_h1_h[NROWS * HID],    g_h1_l[NROWS * HID];
__device__ __nv_bfloat16 g_emb_h[NROWS * EMBD],  g_emb_l[NROWS * EMBD];
__device__ __nv_bfloat16 g_h2_h[NROWS * HID],    g_h2_l[NROWS * HID];
__device__ __nv_bfloat16 g_w1_h[HID * DIN],  g_w1_l[HID * DIN];    // [N,K]
__device__ __nv_bfloat16 g_w2_h[EMBD * HID], g_w2_l[EMBD * HID];
__device__ __nv_bfloat16 g_w3_h[HID * EMBD], g_w3_l[HID * EMBD];
__device__ __nv_bfloat16 g_w4_h[DIN * HID],  g_w4_l[DIN * HID];
__device__ float  g_emb[NROWS * EMBD];
__device__ int    g_lbl[NROWS];
__device__ float  g_sq[NROWS];
__device__ int    g_counts[NCLS], g_off[NCLS], g_cur[NCLS], g_idx[NROWS];
__device__ double g_S[NCLS * NCON];
__device__ double g_Q[NCLS];
__device__ double g_cdiff;

// ======================= small kernels ==========================================
__global__ void k_init() {
    int t = threadIdx.x;
    if (t < NCLS) { g_counts[t] = 0; g_Q[t] = 0.0; }
    if (t == 0) g_cdiff = 0.0;
    for (int i = t; i < NCLS * NCON; i += blockDim.x) g_S[i] = 0.0;
}

__global__ void k_prep(const float* __restrict__ x) {
    const int total = NROWS * (DIN + 1);
    for (int e = blockIdx.x * blockDim.x + threadIdx.x; e < total;
         e += gridDim.x * blockDim.x) {
        int i = e / (DIN + 1);
        int j = e - i * (DIN + 1);
        float v = x[e];
        if (j == 0) {
            int c = (int)v;
            g_lbl[i] = c;
            atomicAdd(&g_counts[c], 1);
        } else {
            __nv_bfloat16 h = __float2bfloat16(v);
            float lo = v - __bfloat162float(h);
            int idx = i * DIN + (j - 1);
            g_data_h[idx] = h;
            g_data_l[idx] = __float2bfloat16(lo);
        }
    }
}

// one kernel: transpose + split all four weight matrices W[K,N] -> [N,K] hi/lo
__global__ void k_wt_all(const float* __restrict__ W1, const float* __restrict__ W2,
                         const float* __restrict__ W3, const float* __restrict__ W4) {
    const int S1 = DIN * HID, S2 = HID * EMBD, S3 = EMBD * HID, S4 = HID * DIN;
    const int T1 = S1, T2 = T1 + S2, T3 = T2 + S3, T4 = T3 + S4;
    for (int e = blockIdx.x * blockDim.x + threadIdx.x; e < T4;
         e += gridDim.x * blockDim.x) {
        const float* W;
        __nv_bfloat16 *th, *tl;
        int le, K, N;
        if (e < T1)      { W = W1; th = g_w1_h; tl = g_w1_l; le = e;      K = DIN;  N = HID;  }
        else if (e < T2) { W = W2; th = g_w2_h; tl = g_w2_l; le = e - T1; K = HID;  N = EMBD; }
        else if (e < T3) { W = W3; th = g_w3_h; tl = g_w3_l; le = e - T2; K = EMBD; N = HID;  }
        else             { W = W4; th = g_w4_h; tl = g_w4_l; le = e - T3; K = HID;  N = DIN;  }
        int k = le / N, n = le - k * N;
        float v = W[le];
        __nv_bfloat16 h = __float2bfloat16(v);
        float lo = v - __bfloat162float(h);
        th[n * K + k] = h;
        tl[n * K + k] = __float2bfloat16(lo);
    }
}

__global__ void k_offsets() {
    if (threadIdx.x == 0) {
        int s = 0;
        for (int c = 0; c < NCLS; c++) { g_off[c] = s; g_cur[c] = s; s += g_counts[c]; }
    }
}

__global__ void k_scatter() {
    int i = blockIdx.x * blockDim.x + threadIdx.x;
    if (i < NROWS) {
        int c = g_lbl[i];
        int p = atomicAdd(&g_cur[c], 1);
        g_idx[p] = i;
    }
}

// ======================= mma.sync bf16-split GEMM ===============================
// C[M,N] = act(A[M,K] @ Bt[N,K]^T + bias); 3 products Ah*Bh + Ah*Bl + Al*Bh.
// CTA: 256 thr = WR x WC warps; tile MT x NT; K chunks 32; cp.async 2-stage.
// Per-nj: both B hi/lo fragments in temps, 12 MMAs spaced 4 apart per accumulator.
template<int MT, int NT, int WR, int WC>
__global__ __launch_bounds__(256, 2)
void k_gemm_mma(const __nv_bfloat16* __restrict__ Ah, const __nv_bfloat16* __restrict__ Al,
                const __nv_bfloat16* __restrict__ Bh, const __nv_bfloat16* __restrict__ Bl,
                const float* __restrict__ bias, float* __restrict__ f32out,
                __nv_bfloat16* __restrict__ oh, __nv_bfloat16* __restrict__ ol,
                int K, int N, int act) {
    constexpr int MI   = MT / (WR * 16);   // m16 frags per warp
    constexpr int WN   = NT / WC;          // warp N tile
    constexpr int NW8  = WN / 8;
    constexpr int NJ   = WN / 16;
    constexpr int MW   = MT / WR;          // warp M tile
    constexpr int STRB = 80;               // smem row stride bytes (32 bf16 + 8 pad)
    constexpr int ABY  = MT * STRB;
    constexpr int BBY  = NT * STRB;
    constexpr int OFF_AL = ABY;
    constexpr int OFF_BH = 2 * ABY;
    constexpr int OFF_BL = 2 * ABY + BBY;
    constexpr int BUFSZ  = 2 * ABY + 2 * BBY;

    extern __shared__ __align__(16) char smem[];
    const uint32_t sbase = smem_u32(smem);

    const int tid = threadIdx.x;
    const int wid = tid >> 5, lane = tid & 31;
    const int wr = wid / WC, wc = wid % WC;
    const int bm = blockIdx.y * MT, bn = blockIdx.x * NT;

    float acc[MI][NW8][4];
#pragma unroll
    for (int a = 0; a < MI; a++)
#pragma unroll
        for (int b = 0; b < NW8; b++)
#pragma unroll
            for (int c = 0; c < 4; c++) acc[a][b][c] = 0.f;

    const int nch = K >> 5;

    auto load_chunk = [&](int buf, int kc) {
        const int k0 = kc << 5;
        const uint32_t sb = sbase + buf * BUFSZ;
        for (int u = tid; u < MT * 4; u += 256) {
            int r = u >> 2, s = u & 3;
            size_t go = (size_t)(bm + r) * K + k0 + s * 8;
            uint32_t so = (uint32_t)(r * STRB + s * 16);
            ld16(sb + so, Ah + go);
            ld16(sb + OFF_AL + so, Al + go);
        }
        for (int u = tid; u < NT * 4; u += 256) {
            int r = u >> 2, s = u & 3;
            size_t go = (size_t)(bn + r) * K + k0 + s * 8;
            uint32_t so = (uint32_t)(r * STRB + s * 16);
            ld16(sb + OFF_BH + so, Bh + go);
            ld16(sb + OFF_BL + so, Bl + go);
        }
        asm volatile("cp.async.commit_group;" ::: "memory");
    };

    load_chunk(0, 0);
    for (int kc = 0; kc < nch; kc++) {
        if (kc + 1 < nch) {
            load_chunk((kc + 1) & 1, kc + 1);
            asm volatile("cp.async.wait_group 1;" ::: "memory");
        } else {
            asm volatile("cp.async.wait_group 0;" ::: "memory");
        }
        __syncthreads();

        const uint32_t sb = sbase + (kc & 1) * BUFSZ;
#pragma unroll
        for (int ks = 0; ks < 2; ks++) {
            uint32_t ah[MI][4], alr[MI][4];
#pragma unroll
            for (int mi = 0; mi < MI; mi++) {
                uint32_t ar = wr * MW + mi * 16 + (lane & 15);
                uint32_t ac = ks * 16 + (lane >> 4) * 8;
                uint32_t ad = sb + ar * STRB + ac * 2;
                ldsm4(ah[mi], ad);
                ldsm4(alr[mi], ad + OFF_AL);
            }
            uint32_t br = wc * WN + ((lane >> 4) << 3) + (lane & 7);
            uint32_t bc = ks * 16 + ((lane >> 3) & 1) * 8;
#pragma unroll
            for (int nj = 0; nj < NJ; nj++) {
                uint32_t bd = sb + OFF_BH + (br + nj * 16) * STRB + bc * 2;
                uint32_t t[4], u4[4];
                ldsm4(t, bd);
                ldsm4(u4, bd + (OFF_BL - OFF_BH));
                // hi*hi: distance-4 spacing on each accumulator
#pragma unroll
                for (int mi = 0; mi < MI; mi++) {
                    mma16816(acc[mi][2 * nj],     ah[mi], t);
                    mma16816(acc[mi][2 * nj + 1], ah[mi], t + 2);
                }
                // hi*lo
#pragma unroll
                for (int mi = 0; mi < MI; mi++) {
                    mma16816(acc[mi][2 * nj],     ah[mi], u4);
                    mma16816(acc[mi][2 * nj + 1], ah[mi], u4 + 2);
                }
                // lo*hi
#pragma unroll
                for (int mi = 0; mi < MI; mi++) {
                    mma16816(acc[mi][2 * nj],     alr[mi], t);
                    mma16816(acc[mi][2 * nj + 1], alr[mi], t + 2);
                }
            }
        }
        __syncthreads();
    }

    // epilogue: bias + optional tanh, direct stores (float2 / bf16x2 pairs)
    const int g = lane >> 2, i2 = (lane & 3) * 2;
#pragma unroll
    for (int mi = 0; mi < MI; mi++) {
#pragma unroll
        for (int ni = 0; ni < NW8; ni++) {
            int col = bn + wc * WN + ni * 8 + i2;
            float b0 = bias[col], b1 = bias[col + 1];
#pragma unroll
            for (int h = 0; h < 2; h++) {
                int row = bm + wr * MW + mi * 16 + g + h * 8;
                float v0 = acc[mi][ni][2 * h] + b0;
                float v1 = acc[mi][ni][2 * h + 1] + b1;
                if (act) { v0 = tanhf(v0); v1 = tanhf(v1); }
                size_t oi = (size_t)row * N + col;
                if (f32out) *(float2*)(f32out + oi) = make_float2(v0, v1);
                if (oh) {
                    __nv_bfloat16 h0 = __float2bfloat16(v0);
                    __nv_bfloat16 h1 = __float2bfloat16(v1);
                    float l0 = v0 - __bfloat162float(h0);
                    float l1 = v1 - __bfloat162float(h1);
                    *(__nv_bfloat162*)(oh + oi) = __halves2bfloat162(h0, h1);
                    *(__nv_bfloat162*)(ol + oi) =
                        __halves2bfloat162(__float2bfloat16(l0), __float2bfloat16(l1));
                }
            }
        }
    }
}

// ======================= embedding stats ========================================
__global__ void k_sq() {
    int row  = blockIdx.x * 8 + (threadIdx.x >> 5);
    int lane = threadIdx.x & 31;
    float s = 0.f;
    for (int d = lane; d < NCON; d += 32) {
        float v = g_emb[row * EMBD + 2 + d];
        s += v * v;
    }
#pragma unroll
    for (int o = 16; o; o >>= 1) s += __shfl_xor_sync(0xffffffff, s, o);
    if (lane == 0) {
        g_sq[row] = s;
        atomicAdd(&g_Q[g_lbl[row]], (double)s);
    }
}

__global__ void k_S() {
    int c = blockIdx.x;
    int d = threadIdx.x;
    if (d >= NCON) return;
    int n = g_counts[c], off = g_off[c];
    double a0 = 0, a1 = 0, a2 = 0, a3 = 0;
    int r = 0;
    for (; r + 4 <= n; r += 4) {
        a0 += (double)g_emb[g_idx[off + r + 0] * EMBD + 2 + d];
        a1 += (double)g_emb[g_idx[off + r + 1] * EMBD + 2 + d];
        a2 += (double)g_emb[g_idx[off + r + 2] * EMBD + 2 + d];
        a3 += (double)g_emb[g_idx[off + r + 3] * EMBD + 2 + d];
    }
    for (; r < n; r++) a0 += (double)g_emb[g_idx[off + r] * EMBD + 2 + d];
    g_S[c * NCON + d] = a0 + a1 + a2 + a3;
}

// ======================= same-class pairwise hinge (triangular) =================
__global__ __launch_bounds__(256)
void k_pairs() {
    const int c   = blockIdx.y;
    const int n   = g_counts[c];
    const int off = g_off[c];
    const int nt  = (n + 63) >> 6;
    const int tot = nt * (nt + 1) / 2;

    __shared__ float  smA[NCON][68];
    __shared__ float  smB[NCON][68];
    __shared__ float  sqA[64], sqB[64];
    __shared__ double red[256];

    const int tid = threadIdx.x;
    const int ty  = tid >> 4, tx = tid & 15;
    double acc = 0.0;

    for (int t = blockIdx.x; t < tot; t += gridDim.x) {
        int rem = t, TI = 0;
        while (rem >= nt - TI) { rem -= nt - TI; TI++; }
        int TJ = TI + rem;
        float w = (TI == TJ) ? 1.0f : 2.0f;
        int i0 = TI * 64, j0 = TJ * 64;
        __syncthreads();
        for (int e = tid; e < NCON * 64; e += 256) {
            int d = e >> 6, r = e & 63;
            int ri = i0 + r, rj = j0 + r;
            smA[d][r] = (ri < n) ? g_emb[g_idx[off + ri] * EMBD + 2 + d] : 0.f;
            smB[d][r] = (rj < n) ? g_emb[g_idx[off + rj] * EMBD + 2 + d] : 0.f;
        }
        if (tid < 64) {
            sqA[tid] = (i0 + tid < n) ? g_sq[g_idx[off + i0 + tid]] : 1e30f;
            sqB[tid] = (j0 + tid < n) ? g_sq[g_idx[off + j0 + tid]] : 1e30f;
        }
        __syncthreads();
        float dot[4][4] = {};
#pragma unroll
        for (int k = 0; k < NCON; k++) {
            float a[4], b[4];
#pragma unroll
            for (int i = 0; i < 4; i++) a[i] = smA[k][ty * 4 + i];
#pragma unroll
            for (int j = 0; j < 4; j++) b[j] = smB[k][tx * 4 + j];
#pragma unroll
            for (int i = 0; i < 4; i++)
#pragma unroll
                for (int j = 0; j < 4; j++) dot[i][j] += a[i] * b[j];
        }
        float ts = 0.f;
#pragma unroll
        for (int i = 0; i < 4; i++) {
            float si = sqA[ty * 4 + i];
#pragma unroll
            for (int j = 0; j < 4; j++) {
                float df = si + sqB[tx * 4 + j] - 2.f * dot[i][j];
                float dm = fmaxf(df, 0.f) * (1.0f / 62.0f);
                ts += fmaxf(0.f, MARGINF - dm);
            }
        }
        acc += (double)(w * ts);
    }
    red[tid] = acc;
    __syncthreads();
    for (int o = 128; o; o >>= 1) {
        if (tid < o) red[tid] += red[tid + o];
        __syncthreads();
    }
    if (tid == 0 && red[0] != 0.0) atomicAdd(&g_cdiff, red[0]);
}

// ======================= finalize scalars =======================================
__global__ void k_final(float* __restrict__ out) {
    __shared__ double shA[64], shB[64];
    int d = threadIdx.x;
    double sgd = 0.0, s2c = 0.0;
    if (d < NCON) {
        for (int c = 0; c < NCLS; c++) {
            double v = g_S[c * NCON + d];
            sgd += v;
            s2c += v * v;
        }
    }
    shA[d] = sgd * sgd;
    shB[d] = s2c;
    __syncthreads();
    if (d == 0) {
        double S2g = 0.0, S2c = 0.0;
        for (int k = 0; k < 64; k++) { S2g += shA[k]; S2c += shB[k]; }
        double T = 0.0, sumn2 = 0.0, snq = 0.0;
        for (int c = 0; c < NCLS; c++) {
            double nc = (double)g_counts[c];
            T     += g_Q[c];
            sumn2 += nc * nc;
            snq   += 2.0 * nc * g_Q[c];
        }
        double Nd     = (double)NROWS;
        double n_diff = Nd * Nd - sumn2;
        double sum_all  = 2.0 * Nd * T - 2.0 * S2g;
        double sum_same = snq - 2.0 * S2c;
        double C_sim  = (sum_all - sum_same) / 62.0 / (n_diff + 1.0);
        double C_diff = g_cdiff / (Nd * Nd - n_diff + 1.0);
        out[OUT_OFF + 0] = (float)C_sim;
        out[OUT_OFF + 1] = (float)C_diff;
    }
}

// ======================= launch =================================================
extern "C" void kernel_launch(void* const* d_in, const int* in_sizes, int n_in,
                              void* d_out, int out_size) {
    const float* x  = (const float*)d_in[0];
    const float* W1 = (const float*)d_in[1];
    const float* b1 = (const float*)d_in[2];
    const float* W2 = (const float*)d_in[3];
    const float* b2 = (const float*)d_in[4];
    const float* W3 = (const float*)d_in[5];
    const float* b3 = (const float*)d_in[6];
    const float* W4 = (const float*)d_in[7];
    const float* b4 = (const float*)d_in[8];
    float* out = (float*)d_out;

    // big config: 128x128 tile, 4x2 warps -> 81920B dyn smem
    cudaFuncSetAttribute((const void*)k_gemm_mma<128, 128, 4, 2>,
                         cudaFuncAttributeMaxDynamicSharedMemorySize, 81920);
    // L2 config: 64x32 tile, 4x2 warps -> 30720B dyn smem
    cudaFuncSetAttribute((const void*)k_gemm_mma<64, 32, 4, 2>,
                         cudaFuncAttributeMaxDynamicSharedMemorySize, 30720);

    __nv_bfloat16 *dh, *dl, *h1h, *h1l, *eh, *el, *h2h, *h2l;
    __nv_bfloat16 *w1h, *w1l, *w2h, *w2l, *w3h, *w3l, *w4h, *w4l;
    float* pemb;
    cudaGetSymbolAddress((void**)&dh,  g_data_h); cudaGetSymbolAddress((void**)&dl,  g_data_l);
    cudaGetSymbolAddress((void**)&h1h, g_h1_h);   cudaGetSymbolAddress((void**)&h1l, g_h1_l);
    cudaGetSymbolAddress((void**)&eh,  g_emb_h);  cudaGetSymbolAddress((void**)&el,  g_emb_l);
    cudaGetSymbolAddress((void**)&h2h, g_h2_h);   cudaGetSymbolAddress((void**)&h2l, g_h2_l);
    cudaGetSymbolAddress((void**)&w1h, g_w1_h);   cudaGetSymbolAddress((void**)&w1l, g_w1_l);
    cudaGetSymbolAddress((void**)&w2h, g_w2_h);   cudaGetSymbolAddress((void**)&w2l, g_w2_l);
    cudaGetSymbolAddress((void**)&w3h, g_w3_h);   cudaGetSymbolAddress((void**)&w3l, g_w3_l);
    cudaGetSymbolAddress((void**)&w4h, g_w4_h);   cudaGetSymbolAddress((void**)&w4l, g_w4_l);
    cudaGetSymbolAddress((void**)&pemb, g_emb);

    k_init<<<1, 1024>>>();                                   // my #0
    k_prep<<<4096, 256>>>(x);                                // my #1
    k_wt_all<<<2304, 256>>>(W1, W2, W3, W4);                 // my #2

    // L1: h1 = tanh(data @ W1 + b1)  [8192,1024], K=512 --- my #3 (ncu target)
    k_gemm_mma<128, 128, 4, 2><<<dim3(HID / 128, NROWS / 128), 256, 81920>>>(
        dh, dl, w1h, w1l, b1, nullptr, h1h, h1l, DIN, HID, 1);

    k_offsets<<<1, 32>>>();
    k_scatter<<<32, 256>>>();

    // L2: emb = h1 @ W2 + b2         [8192,64], K=1024 -- 64x32 tiles, 256 CTAs
    k_gemm_mma<64, 32, 4, 2><<<dim3(EMBD / 32, NROWS / 64), 256, 30720>>>(
        h1h, h1l, w2h, w2l, b2, pemb, eh, el, HID, EMBD, 0);
    k_sq<<<NROWS / 8, 256>>>();
    k_S<<<NCLS, 64>>>();
    // L3: h2 = tanh(emb @ W3 + b3)   [8192,1024], K=64
    k_gemm_mma<128, 128, 4, 2><<<dim3(HID / 128, NROWS / 128), 256, 81920>>>(
        eh, el, w3h, w3l, b3, nullptr, h2h, h2l, EMBD, HID, 1);
    // L4: decoded = h2 @ W4 + b4 -> d_out  [8192,512], K=1024
    k_gemm_mma<128, 128, 4, 2><<<dim3(DIN / 128, NROWS / 128), 256, 81920>>>(
        h2h, h2l, w4h, w4l, b4, out, nullptr, nullptr, HID, DIN, 0);

    k_pairs<<<dim3(40, NCLS), 256>>>();
    k_final<<<1, 64>>>(out);
}

// round 6
// speedup vs baseline: 1.9632x; 1.0213x over previous
#include <cuda_runtime.h>
#include <cuda_bf16.h>
#include <cstdint>
#include <math.h>

#define NROWS 8192
#define DIN   512
#define HID   1024
#define EMBD  64
#define NCON  62
#define NCLS  16
#define MARGINF 0.01f
#define OUT_OFF (NROWS * DIN)

// ======================= helpers ================================================
__device__ __forceinline__ void ld16(uint32_t s, const void* g) {
    asm volatile("cp.async.cg.shared.global [%0], [%1], 16;" :: "r"(s), "l"(g));
}
__device__ __forceinline__ uint32_t smem_u32(const void* p) {
    uint32_t a;
    asm("{ .reg .u64 t; cvta.to.shared.u64 t, %1; cvt.u32.u64 %0, t; }" : "=r"(a) : "l"(p));
    return a;
}
__device__ __forceinline__ void ldsm4(uint32_t* r, uint32_t addr) {
    asm volatile("ldmatrix.sync.aligned.m8n8.x4.shared.b16 {%0,%1,%2,%3}, [%4];"
        : "=r"(r[0]), "=r"(r[1]), "=r"(r[2]), "=r"(r[3]) : "r"(addr));
}
__device__ __forceinline__ void mma16816(float* c, const uint32_t* a, const uint32_t* b) {
    asm volatile("mma.sync.aligned.m16n8k16.row.col.f32.bf16.bf16.f32 "
        "{%0,%1,%2,%3}, {%4,%5,%6,%7}, {%8,%9}, {%0,%1,%2,%3};"
        : "+f"(c[0]), "+f"(c[1]), "+f"(c[2]), "+f"(c[3])
        : "r"(a[0]), "r"(a[1]), "r"(a[2]), "r"(a[3]), "r"(b[0]), "r"(b[1]));
}

// ======================= scratch (device globals) ===============================
__device__ __nv_bfloat16 g_data_h[NROWS * DIN],  g_data_l[NROWS * DIN];
__device__ __nv_bfloat16 g_h1_h[NROWS * HID],    g_h1_l[NROWS * HID];
__device__ __nv_bfloat16 g_emb_h[NROWS * EMBD],  g_emb_l[NROWS * EMBD];
__device__ __nv_bfloat16 g_h2_h[NROWS * HID],    g_h2_l[NROWS * HID];
__device__ __nv_bfloat16 g_w1_h[HID * DIN],  g_w1_l[HID * DIN];    // [N,K]
__device__ __nv_bfloat16 g_w2_h[EMBD * HID], g_w2_l[EMBD * HID];
__device__ __nv_bfloat16 g_w3_h[HID * EMBD], g_w3_l[HID * EMBD];
__device__ __nv_bfloat16 g_w4_h[DIN * HID],  g_w4_l[DIN * HID];
__device__ float  g_emb[NROWS * EMBD];
__device__ int    g_lbl[NROWS];
__device__ float  g_sq[NROWS];
__device__ int    g_counts[NCLS], g_off[NCLS], g_cur[NCLS], g_idx[NROWS];
__device__ double g_S[NCLS * NCON];
__device__ double g_Q[NCLS];
__device__ double g_cdiff;

// ======================= small kernels ==========================================
__global__ void k_init() {
    int t = threadIdx.x;
    if (t < NCLS) { g_counts[t] = 0; g_Q[t] = 0.0; }
    if (t == 0) g_cdiff = 0.0;
    for (int i = t; i < NCLS * NCON; i += blockDim.x) g_S[i] = 0.0;
}

__global__ void k_prep(const float* __restrict__ x) {
    const int total = NROWS * (DIN + 1);
    for (int e = blockIdx.x * blockDim.x + threadIdx.x; e < total;
         e += gridDim.x * blockDim.x) {
        int i = e / (DIN + 1);
        int j = e - i * (DIN + 1);
        float v = x[e];
        if (j == 0) {
            int c = (int)v;
            g_lbl[i] = c;
            atomicAdd(&g_counts[c], 1);
        } else {
            __nv_bfloat16 h = __float2bfloat16(v);
            float lo = v - __bfloat162float(h);
            int idx = i * DIN + (j - 1);
            g_data_h[idx] = h;
            g_data_l[idx] = __float2bfloat16(lo);
        }
    }
}

// one kernel: transpose + split all four weight matrices W[K,N] -> [N,K] hi/lo
__global__ void k_wt_all(const float* __restrict__ W1, const float* __restrict__ W2,
                         const float* __restrict__ W3, const float* __restrict__ W4) {
    const int S1 = DIN * HID, S2 = HID * EMBD, S3 = EMBD * HID, S4 = HID * DIN;
    const int T1 = S1, T2 = T1 + S2, T3 = T2 + S3, T4 = T3 + S4;
    for (int e = blockIdx.x * blockDim.x + threadIdx.x; e < T4;
         e += gridDim.x * blockDim.x) {
        const float* W;
        __nv_bfloat16 *th, *tl;
        int le, K, N;
        if (e < T1)      { W = W1; th = g_w1_h; tl = g_w1_l; le = e;      K = DIN;  N = HID;  }
        else if (e < T2) { W = W2; th = g_w2_h; tl = g_w2_l; le = e - T1; K = HID;  N = EMBD; }
        else if (e < T3) { W = W3; th = g_w3_h; tl = g_w3_l; le = e - T2; K = EMBD; N = HID;  }
        else             { W = W4; th = g_w4_h; tl = g_w4_l; le = e - T3; K = HID;  N = DIN;  }
        int k = le / N, n = le - k * N;
        float v = W[le];
        __nv_bfloat16 h = __float2bfloat16(v);
        float lo = v - __bfloat162float(h);
        th[n * K + k] = h;
        tl[n * K + k] = __float2bfloat16(lo);
    }
}

__global__ void k_offsets() {
    if (threadIdx.x == 0) {
        int s = 0;
        for (int c = 0; c < NCLS; c++) { g_off[c] = s; g_cur[c] = s; s += g_counts[c]; }
    }
}

__global__ void k_scatter() {
    int i = blockIdx.x * blockDim.x + threadIdx.x;
    if (i < NROWS) {
        int c = g_lbl[i];
        int p = atomicAdd(&g_cur[c], 1);
        g_idx[p] = i;
    }
}

// ======================= mma.sync bf16-split GEMM ===============================
// C[M,N] = act(A[M,K] @ Bt[N,K]^T + bias); 3 products Ah*Bh + Ah*Bl + Al*Bh.
// CTA: 256 thr = WR x WC warps; tile MT x NT; K chunks 32; cp.async 2-stage.
// MINB CTAs/SM forced via launch bounds (register budget).
template<int MT, int NT, int WR, int WC, int MINB>
__global__ __launch_bounds__(256, MINB)
void k_gemm_mma(const __nv_bfloat16* __restrict__ Ah, const __nv_bfloat16* __restrict__ Al,
                const __nv_bfloat16* __restrict__ Bh, const __nv_bfloat16* __restrict__ Bl,
                const float* __restrict__ bias, float* __restrict__ f32out,
                __nv_bfloat16* __restrict__ oh, __nv_bfloat16* __restrict__ ol,
                int K, int N, int act) {
    constexpr int MI   = MT / (WR * 16);   // m16 frags per warp
    constexpr int WN   = NT / WC;          // warp N tile
    constexpr int NW8  = WN / 8;
    constexpr int NJ   = WN / 16;
    constexpr int MW   = MT / WR;          // warp M tile
    constexpr int STRB = 80;               // smem row stride bytes (32 bf16 + 8 pad)
    constexpr int ABY  = MT * STRB;
    constexpr int BBY  = NT * STRB;
    constexpr int OFF_AL = ABY;
    constexpr int OFF_BH = 2 * ABY;
    constexpr int OFF_BL = 2 * ABY + BBY;
    constexpr int BUFSZ  = 2 * ABY + 2 * BBY;

    extern __shared__ __align__(16) char smem[];
    const uint32_t sbase = smem_u32(smem);

    const int tid = threadIdx.x;
    const int wid = tid >> 5, lane = tid & 31;
    const int wr = wid / WC, wc = wid % WC;
    const int bm = blockIdx.y * MT, bn = blockIdx.x * NT;

    float acc[MI][NW8][4];
#pragma unroll
    for (int a = 0; a < MI; a++)
#pragma unroll
        for (int b = 0; b < NW8; b++)
#pragma unroll
            for (int c = 0; c < 4; c++) acc[a][b][c] = 0.f;

    const int nch = K >> 5;

    auto load_chunk = [&](int buf, int kc) {
        const int k0 = kc << 5;
        const uint32_t sb = sbase + buf * BUFSZ;
        for (int u = tid; u < MT * 4; u += 256) {
            int r = u >> 2, s = u & 3;
            size_t go = (size_t)(bm + r) * K + k0 + s * 8;
            uint32_t so = (uint32_t)(r * STRB + s * 16);
            ld16(sb + so, Ah + go);
            ld16(sb + OFF_AL + so, Al + go);
        }
        for (int u = tid; u < NT * 4; u += 256) {
            int r = u >> 2, s = u & 3;
            size_t go = (size_t)(bn + r) * K + k0 + s * 8;
            uint32_t so = (uint32_t)(r * STRB + s * 16);
            ld16(sb + OFF_BH + so, Bh + go);
            ld16(sb + OFF_BL + so, Bl + go);
        }
        asm volatile("cp.async.commit_group;" ::: "memory");
    };

    load_chunk(0, 0);
    for (int kc = 0; kc < nch; kc++) {
        if (kc + 1 < nch) {
            load_chunk((kc + 1) & 1, kc + 1);
            asm volatile("cp.async.wait_group 1;" ::: "memory");
        } else {
            asm volatile("cp.async.wait_group 0;" ::: "memory");
        }
        __syncthreads();

        const uint32_t sb = sbase + (kc & 1) * BUFSZ;
#pragma unroll
        for (int ks = 0; ks < 2; ks++) {
            uint32_t ah[MI][4], alr[MI][4];
#pragma unroll
            for (int mi = 0; mi < MI; mi++) {
                uint32_t ar = wr * MW + mi * 16 + (lane & 15);
                uint32_t ac = ks * 16 + (lane >> 4) * 8;
                uint32_t ad = sb + ar * STRB + ac * 2;
                ldsm4(ah[mi], ad);
                ldsm4(alr[mi], ad + OFF_AL);
            }
            uint32_t br = wc * WN + ((lane >> 4) << 3) + (lane & 7);
            uint32_t bc = ks * 16 + ((lane >> 3) & 1) * 8;
#pragma unroll
            for (int nj = 0; nj < NJ; nj++) {
                uint32_t bd = sb + OFF_BH + (br + nj * 16) * STRB + bc * 2;
                uint32_t t[4], u4[4];
                ldsm4(t, bd);
                ldsm4(u4, bd + (OFF_BL - OFF_BH));
#pragma unroll
                for (int mi = 0; mi < MI; mi++) {
                    mma16816(acc[mi][2 * nj],     ah[mi], t);
                    mma16816(acc[mi][2 * nj + 1], ah[mi], t + 2);
                }
#pragma unroll
                for (int mi = 0; mi < MI; mi++) {
                    mma16816(acc[mi][2 * nj],     ah[mi], u4);
                    mma16816(acc[mi][2 * nj + 1], ah[mi], u4 + 2);
                }
#pragma unroll
                for (int mi = 0; mi < MI; mi++) {
                    mma16816(acc[mi][2 * nj],     alr[mi], t);
                    mma16816(acc[mi][2 * nj + 1], alr[mi], t + 2);
                }
            }
        }
        __syncthreads();
    }

    // epilogue: bias + optional tanh, direct stores (float2 / bf16x2 pairs)
    const int g = lane >> 2, i2 = (lane & 3) * 2;
#pragma unroll
    for (int mi = 0; mi < MI; mi++) {
#pragma unroll
        for (int ni = 0; ni < NW8; ni++) {
            int col = bn + wc * WN + ni * 8 + i2;
            float b0 = bias[col], b1 = bias[col + 1];
#pragma unroll
            for (int h = 0; h < 2; h++) {
                int row = bm + wr * MW + mi * 16 + g + h * 8;
                float v0 = acc[mi][ni][2 * h] + b0;
                float v1 = acc[mi][ni][2 * h + 1] + b1;
                if (act) { v0 = tanhf(v0); v1 = tanhf(v1); }
                size_t oi = (size_t)row * N + col;
                if (f32out) *(float2*)(f32out + oi) = make_float2(v0, v1);
                if (oh) {
                    __nv_bfloat16 h0 = __float2bfloat16(v0);
                    __nv_bfloat16 h1 = __float2bfloat16(v1);
                    float l0 = v0 - __bfloat162float(h0);
                    float l1 = v1 - __bfloat162float(h1);
                    *(__nv_bfloat162*)(oh + oi) = __halves2bfloat162(h0, h1);
                    *(__nv_bfloat162*)(ol + oi) =
                        __halves2bfloat162(__float2bfloat16(l0), __float2bfloat16(l1));
                }
            }
        }
    }
}

// ======================= embedding stats ========================================
__global__ void k_sq() {
    int row  = blockIdx.x * 8 + (threadIdx.x >> 5);
    int lane = threadIdx.x & 31;
    float s = 0.f;
    for (int d = lane; d < NCON; d += 32) {
        float v = g_emb[row * EMBD + 2 + d];
        s += v * v;
    }
#pragma unroll
    for (int o = 16; o; o >>= 1) s += __shfl_xor_sync(0xffffffff, s, o);
    if (lane == 0) {
        g_sq[row] = s;
        atomicAdd(&g_Q[g_lbl[row]], (double)s);
    }
}

__global__ void k_S() {
    int c = blockIdx.x;
    int d = threadIdx.x;
    if (d >= NCON) return;
    int n = g_counts[c], off = g_off[c];
    double a0 = 0, a1 = 0, a2 = 0, a3 = 0;
    int r = 0;
    for (; r + 4 <= n; r += 4) {
        a0 += (double)g_emb[g_idx[off + r + 0] * EMBD + 2 + d];
        a1 += (double)g_emb[g_idx[off + r + 1] * EMBD + 2 + d];
        a2 += (double)g_emb[g_idx[off + r + 2] * EMBD + 2 + d];
        a3 += (double)g_emb[g_idx[off + r + 3] * EMBD + 2 + d];
    }
    for (; r < n; r++) a0 += (double)g_emb[g_idx[off + r] * EMBD + 2 + d];
    g_S[c * NCON + d] = a0 + a1 + a2 + a3;
}

// ======================= same-class pairwise hinge (triangular) =================
__global__ __launch_bounds__(256)
void k_pairs() {
    const int c   = blockIdx.y;
    const int n   = g_counts[c];
    const int off = g_off[c];
    const int nt  = (n + 63) >> 6;
    const int tot = nt * (nt + 1) / 2;

    __shared__ float  smA[NCON][68];
    __shared__ float  smB[NCON][68];
    __shared__ float  sqA[64], sqB[64];
    __shared__ double red[256];

    const int tid = threadIdx.x;
    const int ty  = tid >> 4, tx = tid & 15;
    double acc = 0.0;

    for (int t = blockIdx.x; t < tot; t += gridDim.x) {
        int rem = t, TI = 0;
        while (rem >= nt - TI) { rem -= nt - TI; TI++; }
        int TJ = TI + rem;
        float w = (TI == TJ) ? 1.0f : 2.0f;
        int i0 = TI * 64, j0 = TJ * 64;
        __syncthreads();
        // coalesced: consecutive threads read consecutive dims of one row
        for (int e = tid; e < 64 * 64; e += 256) {
            int r = e >> 6, d = e & 63;
            if (d < NCON) {
                int ri = i0 + r, rj = j0 + r;
                smA[d][r] = (ri < n) ? g_emb[g_idx[off + ri] * EMBD + 2 + d] : 0.f;
                smB[d][r] = (rj < n) ? g_emb[g_idx[off + rj] * EMBD + 2 + d] : 0.f;
            }
        }
        if (tid < 64) {
            sqA[tid] = (i0 + tid < n) ? g_sq[g_idx[off + i0 + tid]] : 1e30f;
            sqB[tid] = (j0 + tid < n) ? g_sq[g_idx[off + j0 + tid]] : 1e30f;
        }
        __syncthreads();
        float dot[4][4] = {};
#pragma unroll
        for (int k = 0; k < NCON; k++) {
            float a[4], b[4];
#pragma unroll
            for (int i = 0; i < 4; i++) a[i] = smA[k][ty * 4 + i];
#pragma unroll
            for (int j = 0; j < 4; j++) b[j] = smB[k][tx * 4 + j];
#pragma unroll
            for (int i = 0; i < 4; i++)
#pragma unroll
                for (int j = 0; j < 4; j++) dot[i][j] += a[i] * b[j];
        }
        float ts = 0.f;
#pragma unroll
        for (int i = 0; i < 4; i++) {
            float si = sqA[ty * 4 + i];
#pragma unroll
            for (int j = 0; j < 4; j++) {
                float df = si + sqB[tx * 4 + j] - 2.f * dot[i][j];
                float dm = fmaxf(df, 0.f) * (1.0f / 62.0f);
                ts += fmaxf(0.f, MARGINF - dm);
            }
        }
        acc += (double)(w * ts);
    }
    red[tid] = acc;
    __syncthreads();
    for (int o = 128; o; o >>= 1) {
        if (tid < o) red[tid] += red[tid + o];
        __syncthreads();
    }
    if (tid == 0 && red[0] != 0.0) atomicAdd(&g_cdiff, red[0]);
}

// ======================= finalize scalars =======================================
__global__ void k_final(float* __restrict__ out) {
    __shared__ double shA[64], shB[64];
    int d = threadIdx.x;
    double sgd = 0.0, s2c = 0.0;
    if (d < NCON) {
        for (int c = 0; c < NCLS; c++) {
            double v = g_S[c * NCON + d];
            sgd += v;
            s2c += v * v;
        }
    }
    shA[d] = sgd * sgd;
    shB[d] = s2c;
    __syncthreads();
    if (d == 0) {
        double S2g = 0.0, S2c = 0.0;
        for (int k = 0; k < 64; k++) { S2g += shA[k]; S2c += shB[k]; }
        double T = 0.0, sumn2 = 0.0, snq = 0.0;
        for (int c = 0; c < NCLS; c++) {
            double nc = (double)g_counts[c];
            T     += g_Q[c];
            sumn2 += nc * nc;
            snq   += 2.0 * nc * g_Q[c];
        }
        double Nd     = (double)NROWS;
        double n_diff = Nd * Nd - sumn2;
        double sum_all  = 2.0 * Nd * T - 2.0 * S2g;
        double sum_same = snq - 2.0 * S2c;
        double C_sim  = (sum_all - sum_same) / 62.0 / (n_diff + 1.0);
        double C_diff = g_cdiff / (Nd * Nd - n_diff + 1.0);
        out[OUT_OFF + 0] = (float)C_sim;
        out[OUT_OFF + 1] = (float)C_diff;
    }
}

// ======================= launch =================================================
extern "C" void kernel_launch(void* const* d_in, const int* in_sizes, int n_in,
                              void* d_out, int out_size) {
    const float* x  = (const float*)d_in[0];
    const float* W1 = (const float*)d_in[1];
    const float* b1 = (const float*)d_in[2];
    const float* W2 = (const float*)d_in[3];
    const float* b2 = (const float*)d_in[4];
    const float* W3 = (const float*)d_in[5];
    const float* b3 = (const float*)d_in[6];
    const float* W4 = (const float*)d_in[7];
    const float* b4 = (const float*)d_in[8];
    float* out = (float*)d_out;

    // big GEMMs: 128x64 tile, 4x2 warps, 3 CTAs/SM -> 61440B dyn smem
    cudaFuncSetAttribute((const void*)k_gemm_mma<128, 64, 4, 2, 3>,
                         cudaFuncAttributeMaxDynamicSharedMemorySize, 61440);
    // L2: 64x32 tile, 4x2 warps, 3 CTAs/SM -> 30720B dyn smem
    cudaFuncSetAttribute((const void*)k_gemm_mma<64, 32, 4, 2, 3>,
                         cudaFuncAttributeMaxDynamicSharedMemorySize, 30720);

    __nv_bfloat16 *dh, *dl, *h1h, *h1l, *eh, *el, *h2h, *h2l;
    __nv_bfloat16 *w1h, *w1l, *w2h, *w2l, *w3h, *w3l, *w4h, *w4l;
    float* pemb;
    cudaGetSymbolAddress((void**)&dh,  g_data_h); cudaGetSymbolAddress((void**)&dl,  g_data_l);
    cudaGetSymbolAddress((void**)&h1h, g_h1_h);   cudaGetSymbolAddress((void**)&h1l, g_h1_l);
    cudaGetSymbolAddress((void**)&eh,  g_emb_h);  cudaGetSymbolAddress((void**)&el,  g_emb_l);
    cudaGetSymbolAddress((void**)&h2h, g_h2_h);   cudaGetSymbolAddress((void**)&h2l, g_h2_l);
    cudaGetSymbolAddress((void**)&w1h, g_w1_h);   cudaGetSymbolAddress((void**)&w1l, g_w1_l);
    cudaGetSymbolAddress((void**)&w2h, g_w2_h);   cudaGetSymbolAddress((void**)&w2l, g_w2_l);
    cudaGetSymbolAddress((void**)&w3h, g_w3_h);   cudaGetSymbolAddress((void**)&w3l, g_w3_l);
    cudaGetSymbolAddress((void**)&w4h, g_w4_h);   cudaGetSymbolAddress((void**)&w4l, g_w4_l);
    cudaGetSymbolAddress((void**)&pemb, g_emb);

    k_init<<<1, 1024>>>();                                   // my #0
    k_prep<<<4096, 256>>>(x);                                // my #1
    k_wt_all<<<2304, 256>>>(W1, W2, W3, W4);                 // my #2

    // L1: h1 = tanh(data @ W1 + b1)  [8192,1024], K=512 --- my #3 (ncu target)
    k_gemm_mma<128, 64, 4, 2, 3><<<dim3(HID / 64, NROWS / 128), 256, 61440>>>(
        dh, dl, w1h, w1l, b1, nullptr, h1h, h1l, DIN, HID, 1);

    k_offsets<<<1, 32>>>();
    k_scatter<<<32, 256>>>();

    // L2: emb = h1 @ W2 + b2         [8192,64], K=1024 -- 64x32 tiles, 512 CTAs
    k_gemm_mma<64, 32, 4, 2, 3><<<dim3(EMBD / 32, NROWS / 64), 256, 30720>>>(
        h1h, h1l, w2h, w2l, b2, pemb, eh, el, HID, EMBD, 0);
    k_sq<<<NROWS / 8, 256>>>();
    k_S<<<NCLS, 64>>>();
    // L3: h2 = tanh(emb @ W3 + b3)   [8192,1024], K=64
    k_gemm_mma<128, 64, 4, 2, 3><<<dim3(HID / 64, NROWS / 128), 256, 61440>>>(
        eh, el, w3h, w3l, b3, nullptr, h2h, h2l, EMBD, HID, 1);
    // L4: decoded = h2 @ W4 + b4 -> d_out  [8192,512], K=1024
    k_gemm_mma<128, 64, 4, 2, 3><<<dim3(DIN / 64, NROWS / 128), 256, 61440>>>(
        h2h, h2l, w4h, w4l, b4, out, nullptr, nullptr, HID, DIN, 0);

    k_pairs<<<dim3(40, NCLS), 256>>>();
    k_final<<<1, 64>>>(out);
}

// round 8
// speedup vs baseline: 2.1020x; 1.0707x over previous
#include <cuda_runtime.h>
#include <cuda_bf16.h>
#include <cstdint>
#include <math.h>

#define NROWS 8192
#define DIN   512
#define HID   1024
#define EMBD  64
#define NCON  62
#define NCLS  16
#define MARGINF 0.01f
#define OUT_OFF (NROWS * DIN)

// ======================= helpers ================================================
__device__ __forceinline__ void ld16(uint32_t s, const void* g) {
    asm volatile("cp.async.cg.shared.global [%0], [%1], 16;" :: "r"(s), "l"(g));
}
__device__ __forceinline__ uint32_t smem_u32(const void* p) {
    uint32_t a;
    asm("{ .reg .u64 t; cvta.to.shared.u64 t, %1; cvt.u32.u64 %0, t; }" : "=r"(a) : "l"(p));
    return a;
}
__device__ __forceinline__ void ldsm4(uint32_t* r, uint32_t addr) {
    asm volatile("ldmatrix.sync.aligned.m8n8.x4.shared.b16 {%0,%1,%2,%3}, [%4];"
        : "=r"(r[0]), "=r"(r[1]), "=r"(r[2]), "=r"(r[3]) : "r"(addr));
}
__device__ __forceinline__ void mma16816(float* c, const uint32_t* a, const uint32_t* b) {
    asm volatile("mma.sync.aligned.m16n8k16.row.col.f32.bf16.bf16.f32 "
        "{%0,%1,%2,%3}, {%4,%5,%6,%7}, {%8,%9}, {%0,%1,%2,%3};"
        : "+f"(c[0]), "+f"(c[1]), "+f"(c[2]), "+f"(c[3])
        : "r"(a[0]), "r"(a[1]), "r"(a[2]), "r"(a[3]), "r"(b[0]), "r"(b[1]));
}

// ======================= scratch (device globals) ===============================
__device__ __nv_bfloat16 g_data_h[NROWS * DIN],  g_data_l[NROWS * DIN];
__device__ __nv_bfloat16 g_h1_h[NROWS * HID],    g_h1_l[NROWS * HID];
__device__ __nv_bfloat16 g_emb_h[NROWS * EMBD],  g_emb_l[NROWS * EMBD];
__device__ __nv_bfloat16 g_h2_h[NROWS * HID],    g_h2_l[NROWS * HID];
__device__ __nv_bfloat16 g_w1_h[HID * DIN],  g_w1_l[HID * DIN];    // [N,K]
__device__ __nv_bfloat16 g_w2_h[EMBD * HID], g_w2_l[EMBD * HID];
__device__ __nv_bfloat16 g_w3_h[HID * EMBD], g_w3_l[HID * EMBD];
__device__ __nv_bfloat16 g_w4_h[DIN * HID],  g_w4_l[DIN * HID];
__device__ float  g_emb[NROWS * EMBD];
__device__ int    g_lbl[NROWS];
__device__ float  g_sq[NROWS];
__device__ int    g_counts[NCLS], g_off[NCLS], g_cur[NCLS], g_idx[NROWS];
__device__ double g_S[NCLS * NCON];
__device__ double g_Q[NCLS];
__device__ double g_cdiff;

// ======================= small kernels ==========================================
__global__ void k_init() {
    int t = threadIdx.x;
    if (t < NCLS) { g_counts[t] = 0; g_Q[t] = 0.0; }
    if (t == 0) g_cdiff = 0.0;
    for (int i = t; i < NCLS * NCON; i += blockDim.x) g_S[i] = 0.0;
}

__global__ void k_prep(const float* __restrict__ x) {
    const int total = NROWS * (DIN + 1);
    for (int e = blockIdx.x * blockDim.x + threadIdx.x; e < total;
         e += gridDim.x * blockDim.x) {
        int i = e / (DIN + 1);
        int j = e - i * (DIN + 1);
        float v = x[e];
        if (j == 0) {
            int c = (int)v;
            g_lbl[i] = c;
            atomicAdd(&g_counts[c], 1);
        } else {
            __nv_bfloat16 h = __float2bfloat16(v);
            float lo = v - __bfloat162float(h);
            int idx = i * DIN + (j - 1);
            g_data_h[idx] = h;
            g_data_l[idx] = __float2bfloat16(lo);
        }
    }
}

// transpose + split all four weight matrices W[K,N] -> [N,K] bf16 hi/lo
__global__ void k_wt_all(const float* __restrict__ W1, const float* __restrict__ W2,
                         const float* __restrict__ W3, const float* __restrict__ W4) {
    const int S1 = DIN * HID, S2 = HID * EMBD, S3 = EMBD * HID, S4 = HID * DIN;
    const int T1 = S1, T2 = T1 + S2, T3 = T2 + S3, T4 = T3 + S4;
    for (int e = blockIdx.x * blockDim.x + threadIdx.x; e < T4;
         e += gridDim.x * blockDim.x) {
        const float* W;
        __nv_bfloat16 *th, *tl;
        int le, K, N;
        if (e < T1)      { W = W1; th = g_w1_h; tl = g_w1_l; le = e;      K = DIN;  N = HID;  }
        else if (e < T2) { W = W2; th = g_w2_h; tl = g_w2_l; le = e - T1; K = HID;  N = EMBD; }
        else if (e < T3) { W = W3; th = g_w3_h; tl = g_w3_l; le = e - T2; K = EMBD; N = HID;  }
        else             { W = W4; th = g_w4_h; tl = g_w4_l; le = e - T3; K = HID;  N = DIN;  }
        int k = le / N, n = le - k * N;
        float v = W[le];
        __nv_bfloat16 h = __float2bfloat16(v);
        float lo = v - __bfloat162float(h);
        th[n * K + k] = h;
        tl[n * K + k] = __float2bfloat16(lo);
    }
}

__global__ void k_offsets() {
    if (threadIdx.x == 0) {
        int s = 0;
        for (int c = 0; c < NCLS; c++) { g_off[c] = s; g_cur[c] = s; s += g_counts[c]; }
    }
}

__global__ void k_scatter() {
    int i = blockIdx.x * blockDim.x + threadIdx.x;
    if (i < NROWS) {
        int c = g_lbl[i];
        int p = atomicAdd(&g_cur[c], 1);
        g_idx[p] = i;
    }
}

// ======================= mma.sync bf16-split GEMM ===============================
template<int MT, int NT, int WR, int WC, int MINB>
__global__ __launch_bounds__(256, MINB)
void k_gemm_mma(const __nv_bfloat16* __restrict__ Ah, const __nv_bfloat16* __restrict__ Al,
                const __nv_bfloat16* __restrict__ Bh, const __nv_bfloat16* __restrict__ Bl,
                const float* __restrict__ bias, float* __restrict__ f32out,
                __nv_bfloat16* __restrict__ oh, __nv_bfloat16* __restrict__ ol,
                int K, int N, int act) {
    constexpr int MI   = MT / (WR * 16);
    constexpr int WN   = NT / WC;
    constexpr int NW8  = WN / 8;
    constexpr int NJ   = WN / 16;
    constexpr int MW   = MT / WR;
    constexpr int STRB = 80;
    constexpr int ABY  = MT * STRB;
    constexpr int BBY  = NT * STRB;
    constexpr int OFF_AL = ABY;
    constexpr int OFF_BH = 2 * ABY;
    constexpr int OFF_BL = 2 * ABY + BBY;
    constexpr int BUFSZ  = 2 * ABY + 2 * BBY;

    extern __shared__ __align__(16) char smem[];
    const uint32_t sbase = smem_u32(smem);

    const int tid = threadIdx.x;
    const int wid = tid >> 5, lane = tid & 31;
    const int wr = wid / WC, wc = wid % WC;
    const int bm = blockIdx.y * MT, bn = blockIdx.x * NT;

    float acc[MI][NW8][4];
#pragma unroll
    for (int a = 0; a < MI; a++)
#pragma unroll
        for (int b = 0; b < NW8; b++)
#pragma unroll
            for (int c = 0; c < 4; c++) acc[a][b][c] = 0.f;

    const int nch = K >> 5;

    auto load_chunk = [&](int buf, int kc) {
        const int k0 = kc << 5;
        const uint32_t sb = sbase + buf * BUFSZ;
        for (int u = tid; u < MT * 4; u += 256) {
            int r = u >> 2, s = u & 3;
            size_t go = (size_t)(bm + r) * K + k0 + s * 8;
            uint32_t so = (uint32_t)(r * STRB + s * 16);
            ld16(sb + so, Ah + go);
            ld16(sb + OFF_AL + so, Al + go);
        }
        for (int u = tid; u < NT * 4; u += 256) {
            int r = u >> 2, s = u & 3;
            size_t go = (size_t)(bn + r) * K + k0 + s * 8;
            uint32_t so = (uint32_t)(r * STRB + s * 16);
            ld16(sb + OFF_BH + so, Bh + go);
            ld16(sb + OFF_BL + so, Bl + go);
        }
        asm volatile("cp.async.commit_group;" ::: "memory");
    };

    load_chunk(0, 0);
    for (int kc = 0; kc < nch; kc++) {
        if (kc + 1 < nch) {
            load_chunk((kc + 1) & 1, kc + 1);
            asm volatile("cp.async.wait_group 1;" ::: "memory");
        } else {
            asm volatile("cp.async.wait_group 0;" ::: "memory");
        }
        __syncthreads();

        const uint32_t sb = sbase + (kc & 1) * BUFSZ;
#pragma unroll
        for (int ks = 0; ks < 2; ks++) {
            uint32_t ah[MI][4], alr[MI][4];
#pragma unroll
            for (int mi = 0; mi < MI; mi++) {
                uint32_t ar = wr * MW + mi * 16 + (lane & 15);
                uint32_t ac = ks * 16 + (lane >> 4) * 8;
                uint32_t ad = sb + ar * STRB + ac * 2;
                ldsm4(ah[mi], ad);
                ldsm4(alr[mi], ad + OFF_AL);
            }
            uint32_t br = wc * WN + ((lane >> 4) << 3) + (lane & 7);
            uint32_t bc = ks * 16 + ((lane >> 3) & 1) * 8;
#pragma unroll
            for (int nj = 0; nj < NJ; nj++) {
                uint32_t bd = sb + OFF_BH + (br + nj * 16) * STRB + bc * 2;
                uint32_t t[4], u4[4];
                ldsm4(t, bd);
                ldsm4(u4, bd + (OFF_BL - OFF_BH));
#pragma unroll
                for (int mi = 0; mi < MI; mi++) {
                    mma16816(acc[mi][2 * nj],     ah[mi], t);
                    mma16816(acc[mi][2 * nj + 1], ah[mi], t + 2);
                }
#pragma unroll
                for (int mi = 0; mi < MI; mi++) {
                    mma16816(acc[mi][2 * nj],     ah[mi], u4);
                    mma16816(acc[mi][2 * nj + 1], ah[mi], u4 + 2);
                }
#pragma unroll
                for (int mi = 0; mi < MI; mi++) {
                    mma16816(acc[mi][2 * nj],     alr[mi], t);
                    mma16816(acc[mi][2 * nj + 1], alr[mi], t + 2);
                }
            }
        }
        __syncthreads();
    }

    const int g = lane >> 2, i2 = (lane & 3) * 2;
#pragma unroll
    for (int mi = 0; mi < MI; mi++) {
#pragma unroll
        for (int ni = 0; ni < NW8; ni++) {
            int col = bn + wc * WN + ni * 8 + i2;
            float b0 = bias[col], b1 = bias[col + 1];
#pragma unroll
            for (int h = 0; h < 2; h++) {
                int row = bm + wr * MW + mi * 16 + g + h * 8;
                float v0 = acc[mi][ni][2 * h] + b0;
                float v1 = acc[mi][ni][2 * h + 1] + b1;
                if (act) { v0 = tanhf(v0); v1 = tanhf(v1); }
                size_t oi = (size_t)row * N + col;
                if (f32out) *(float2*)(f32out + oi) = make_float2(v0, v1);
                if (oh) {
                    __nv_bfloat16 h0 = __float2bfloat16(v0);
                    __nv_bfloat16 h1 = __float2bfloat16(v1);
                    float l0 = v0 - __bfloat162float(h0);
                    float l1 = v1 - __bfloat162float(h1);
                    *(__nv_bfloat162*)(oh + oi) = __halves2bfloat162(h0, h1);
                    *(__nv_bfloat162*)(ol + oi) =
                        __halves2bfloat162(__float2bfloat16(l0), __float2bfloat16(l1));
                }
            }
        }
    }
}

// ======================= fused per-class stats: sq, Q, S ========================
__global__ __launch_bounds__(256)
void k_stats() {
    __shared__ double sS[8][64];
    __shared__ double sQ[8];
    const int c = blockIdx.x;
    const int n = g_counts[c], off = g_off[c];
    const int w = threadIdx.x >> 5, lane = threadIdx.x & 31;

    double s0 = 0.0, s1 = 0.0, q = 0.0;
    for (int r = w; r < n; r += 8) {
        int row = g_idx[off + r];
        const float* e = g_emb + row * EMBD + 2;
        float v0 = e[lane];
        float v1 = (lane < NCON - 32) ? e[lane + 32] : 0.f;
        s0 += (double)v0;
        s1 += (double)v1;
        float sq = v0 * v0 + v1 * v1;
#pragma unroll
        for (int o = 16; o; o >>= 1) sq += __shfl_xor_sync(0xffffffff, sq, o);
        if (lane == 0) { g_sq[row] = sq; q += (double)sq; }
    }
    sS[w][lane] = s0;
    sS[w][lane + 32] = s1;
    if (lane == 0) sQ[w] = q;
    __syncthreads();
    int d = threadIdx.x;
    if (d < NCON) {
        double s = 0.0;
        for (int k = 0; k < 8; k++) s += sS[k][d];
        g_S[c * NCON + d] = s;
    }
    if (d == 64) {
        double s = 0.0;
        for (int k = 0; k < 8; k++) s += sQ[k];
        g_Q[c] = s;
    }
}

// ======================= same-class pairwise hinge (triangular) =================
__global__ __launch_bounds__(256)
void k_pairs() {
    const int c   = blockIdx.y;
    const int n   = g_counts[c];
    const int off = g_off[c];
    const int nt  = (n + 63) >> 6;
    const int tot = nt * (nt + 1) / 2;

    __shared__ float  smA[NCON][68];
    __shared__ float  smB[NCON][68];
    __shared__ float  sqA[64], sqB[64];
    __shared__ double red[256];

    const int tid = threadIdx.x;
    const int ty  = tid >> 4, tx = tid & 15;
    double acc = 0.0;

    for (int t = blockIdx.x; t < tot; t += gridDim.x) {
        int rem = t, TI = 0;
        while (rem >= nt - TI) { rem -= nt - TI; TI++; }
        int TJ = TI + rem;
        float w = (TI == TJ) ? 1.0f : 2.0f;
        int i0 = TI * 64, j0 = TJ * 64;
        __syncthreads();
        for (int e = tid; e < 64 * 64; e += 256) {
            int r = e >> 6, d = e & 63;
            if (d < NCON) {
                int ri = i0 + r, rj = j0 + r;
                smA[d][r] = (ri < n) ? g_emb[g_idx[off + ri] * EMBD + 2 + d] : 0.f;
                smB[d][r] = (rj < n) ? g_emb[g_idx[off + rj] * EMBD + 2 + d] : 0.f;
            }
        }
        if (tid < 64) {
            sqA[tid] = (i0 + tid < n) ? g_sq[g_idx[off + i0 + tid]] : 1e30f;
            sqB[tid] = (j0 + tid < n) ? g_sq[g_idx[off + j0 + tid]] : 1e30f;
        }
        __syncthreads();
        float dot[4][4] = {};
#pragma unroll
        for (int k = 0; k < NCON; k++) {
            float a[4], b[4];
#pragma unroll
            for (int i = 0; i < 4; i++) a[i] = smA[k][ty * 4 + i];
#pragma unroll
            for (int j = 0; j < 4; j++) b[j] = smB[k][tx * 4 + j];
#pragma unroll
            for (int i = 0; i < 4; i++)
#pragma unroll
                for (int j = 0; j < 4; j++) dot[i][j] += a[i] * b[j];
        }
        float ts = 0.f;
#pragma unroll
        for (int i = 0; i < 4; i++) {
            float si = sqA[ty * 4 + i];
#pragma unroll
            for (int j = 0; j < 4; j++) {
                float df = si + sqB[tx * 4 + j] - 2.f * dot[i][j];
                float dm = fmaxf(df, 0.f) * (1.0f / 62.0f);
                ts += fmaxf(0.f, MARGINF - dm);
            }
        }
        acc += (double)(w * ts);
    }
    red[tid] = acc;
    __syncthreads();
    for (int o = 128; o; o >>= 1) {
        if (tid < o) red[tid] += red[tid + o];
        __syncthreads();
    }
    if (tid == 0 && red[0] != 0.0) atomicAdd(&g_cdiff, red[0]);
}

// ======================= finalize scalars =======================================
__global__ void k_final(float* __restrict__ out) {
    __shared__ double shA[64], shB[64];
    int d = threadIdx.x;
    double sgd = 0.0, s2c = 0.0;
    if (d < NCON) {
        for (int c = 0; c < NCLS; c++) {
            double v = g_S[c * NCON + d];
            sgd += v;
            s2c += v * v;
        }
    }
    shA[d] = sgd * sgd;
    shB[d] = s2c;
    __syncthreads();
    if (d == 0) {
        double S2g = 0.0, S2c = 0.0;
        for (int k = 0; k < 64; k++) { S2g += shA[k]; S2c += shB[k]; }
        double T = 0.0, sumn2 = 0.0, snq = 0.0;
        for (int c = 0; c < NCLS; c++) {
            double nc = (double)g_counts[c];
            T     += g_Q[c];
            sumn2 += nc * nc;
            snq   += 2.0 * nc * g_Q[c];
        }
        double Nd     = (double)NROWS;
        double n_diff = Nd * Nd - sumn2;
        double sum_all  = 2.0 * Nd * T - 2.0 * S2g;
        double sum_same = snq - 2.0 * S2c;
        double C_sim  = (sum_all - sum_same) / 62.0 / (n_diff + 1.0);
        double C_diff = g_cdiff / (Nd * Nd - n_diff + 1.0);
        out[OUT_OFF + 0] = (float)C_sim;
        out[OUT_OFF + 1] = (float)C_diff;
    }
}

// ======================= launch =================================================
extern "C" void kernel_launch(void* const* d_in, const int* in_sizes, int n_in,
                              void* d_out, int out_size) {
    const float* x  = (const float*)d_in[0];
    const float* W1 = (const float*)d_in[1];
    const float* b1 = (const float*)d_in[2];
    const float* W2 = (const float*)d_in[3];
    const float* b2 = (const float*)d_in[4];
    const float* W3 = (const float*)d_in[5];
    const float* b3 = (const float*)d_in[6];
    const float* W4 = (const float*)d_in[7];
    const float* b4 = (const float*)d_in[8];
    float* out = (float*)d_out;

    // 64x64 tile, 4x2 warps, 4 CTAs/SM -> 40960B dyn smem
    cudaFuncSetAttribute((const void*)k_gemm_mma<64, 64, 4, 2, 4>,
                         cudaFuncAttributeMaxDynamicSharedMemorySize, 40960);
    // L2: 64x32 tile, 4x2 warps, 4 CTAs/SM -> 30720B dyn smem
    cudaFuncSetAttribute((const void*)k_gemm_mma<64, 32, 4, 2, 4>,
                         cudaFuncAttributeMaxDynamicSharedMemorySize, 30720);

    __nv_bfloat16 *dh, *dl, *h1h, *h1l, *eh, *el, *h2h, *h2l;
    __nv_bfloat16 *w1h, *w1l, *w2h, *w2l, *w3h, *w3l, *w4h, *w4l;
    float* pemb;
    cudaGetSymbolAddress((void**)&dh,  g_data_h); cudaGetSymbolAddress((void**)&dl,  g_data_l);
    cudaGetSymbolAddress((void**)&h1h, g_h1_h);   cudaGetSymbolAddress((void**)&h1l, g_h1_l);
    cudaGetSymbolAddress((void**)&eh,  g_emb_h);  cudaGetSymbolAddress((void**)&el,  g_emb_l);
    cudaGetSymbolAddress((void**)&h2h, g_h2_h);   cudaGetSymbolAddress((void**)&h2l, g_h2_l);
    cudaGetSymbolAddress((void**)&w1h, g_w1_h);   cudaGetSymbolAddress((void**)&w1l, g_w1_l);
    cudaGetSymbolAddress((void**)&w2h, g_w2_h);   cudaGetSymbolAddress((void**)&w2l, g_w2_l);
    cudaGetSymbolAddress((void**)&w3h, g_w3_h);   cudaGetSymbolAddress((void**)&w3l, g_w3_l);
    cudaGetSymbolAddress((void**)&w4h, g_w4_h);   cudaGetSymbolAddress((void**)&w4l, g_w4_l);
    cudaGetSymbolAddress((void**)&pemb, g_emb);

    k_init<<<1, 1024>>>();                                   // my #0
    k_prep<<<4096, 256>>>(x);                                // my #1
    k_wt_all<<<2304, 256>>>(W1, W2, W3, W4);                 // my #2

    // L1: h1 = tanh(data @ W1 + b1)  [8192,1024], K=512 --- my #3 (ncu target)
    k_gemm_mma<64, 64, 4, 2, 4><<<dim3(HID / 64, NROWS / 64), 256, 40960>>>(
        dh, dl, w1h, w1l, b1, nullptr, h1h, h1l, DIN, HID, 1);

    k_offsets<<<1, 32>>>();
    k_scatter<<<32, 256>>>();

    // L2: emb = h1 @ W2 + b2         [8192,64], K=1024
    k_gemm_mma<64, 32, 4, 2, 4><<<dim3(EMBD / 32, NROWS / 64), 256, 30720>>>(
        h1h, h1l, w2h, w2l, b2, pemb, eh, el, HID, EMBD, 0);
    k_stats<<<NCLS, 256>>>();
    // L3: h2 = tanh(emb @ W3 + b3)   [8192,1024], K=64
    k_gemm_mma<64, 64, 4, 2, 4><<<dim3(HID / 64, NROWS / 64), 256, 40960>>>(
        eh, el, w3h, w3l, b3, nullptr, h2h, h2l, EMBD, HID, 1);
    // L4: decoded = h2 @ W4 + b4 -> d_out  [8192,512], K=1024
    k_gemm_mma<64, 64, 4, 2, 4><<<dim3(DIN / 64, NROWS / 64), 256, 40960>>>(
        h2h, h2l, w4h, w4l, b4, out, nullptr, nullptr, HID, DIN, 0);

    k_pairs<<<dim3(40, NCLS), 256>>>();
    k_final<<<1, 64>>>(out);
}

// round 9
// speedup vs baseline: 2.2427x; 1.0670x over previous
#include <cuda_runtime.h>
#include <cuda_bf16.h>
#include <cstdint>
#include <math.h>

#define NROWS 8192
#define DIN   512
#define HID   1024
#define EMBD  64
#define NCON  62
#define NCLS  16
#define MARGINF 0.01f
#define OUT_OFF (NROWS * DIN)

// ======================= helpers ================================================
__device__ __forceinline__ void ld16(uint32_t s, const void* g) {
    asm volatile("cp.async.cg.shared.global [%0], [%1], 16;" :: "r"(s), "l"(g));
}
__device__ __forceinline__ uint32_t smem_u32(const void* p) {
    uint32_t a;
    asm("{ .reg .u64 t; cvta.to.shared.u64 t, %1; cvt.u32.u64 %0, t; }" : "=r"(a) : "l"(p));
    return a;
}
__device__ __forceinline__ void ldsm4(uint32_t* r, uint32_t addr) {
    asm volatile("ldmatrix.sync.aligned.m8n8.x4.shared.b16 {%0,%1,%2,%3}, [%4];"
        : "=r"(r[0]), "=r"(r[1]), "=r"(r[2]), "=r"(r[3]) : "r"(addr));
}
__device__ __forceinline__ void mma16816(float* c, const uint32_t* a, const uint32_t* b) {
    asm volatile("mma.sync.aligned.m16n8k16.row.col.f32.bf16.bf16.f32 "
        "{%0,%1,%2,%3}, {%4,%5,%6,%7}, {%8,%9}, {%0,%1,%2,%3};"
        : "+f"(c[0]), "+f"(c[1]), "+f"(c[2]), "+f"(c[3])
        : "r"(a[0]), "r"(a[1]), "r"(a[2]), "r"(a[3]), "r"(b[0]), "r"(b[1]));
}

// ======================= scratch (device globals) ===============================
__device__ __nv_bfloat16 g_data_h[NROWS * DIN],  g_data_l[NROWS * DIN];
__device__ __nv_bfloat16 g_h1_h[NROWS * HID],    g_h1_l[NROWS * HID];
__device__ __nv_bfloat16 g_emb_h[NROWS * EMBD],  g_emb_l[NROWS * EMBD];
__device__ __nv_bfloat16 g_h2_h[NROWS * HID],    g_h2_l[NROWS * HID];
__device__ __nv_bfloat16 g_w1_h[HID * DIN],  g_w1_l[HID * DIN];    // [N,K]
__device__ __nv_bfloat16 g_w2_h[EMBD * HID], g_w2_l[EMBD * HID];
__device__ __nv_bfloat16 g_w3_h[HID * EMBD], g_w3_l[HID * EMBD];
__device__ __nv_bfloat16 g_w4_h[DIN * HID],  g_w4_l[DIN * HID];
__device__ float  g_emb[NROWS * EMBD];
__device__ int    g_lbl[NROWS];
__device__ float  g_sq[NROWS];
__device__ int    g_counts[NCLS], g_off[NCLS], g_cur[NCLS], g_idx[NROWS];
__device__ double g_S[NCLS * NCON];
__device__ double g_Q[NCLS];
__device__ double g_cdiff;

// ======================= small kernels ==========================================
__global__ void k_init() {
    int t = threadIdx.x;
    if (t < NCLS) { g_counts[t] = 0; g_Q[t] = 0.0; }
    if (t == 0) g_cdiff = 0.0;
    for (int i = t; i < NCLS * NCON; i += blockDim.x) g_S[i] = 0.0;
}

__global__ void k_prep(const float* __restrict__ x) {
    const int total = NROWS * (DIN + 1);
    for (int e = blockIdx.x * blockDim.x + threadIdx.x; e < total;
         e += gridDim.x * blockDim.x) {
        int i = e / (DIN + 1);
        int j = e - i * (DIN + 1);
        float v = x[e];
        if (j == 0) {
            int c = (int)v;
            g_lbl[i] = c;
            atomicAdd(&g_counts[c], 1);
        } else {
            __nv_bfloat16 h = __float2bfloat16(v);
            float lo = v - __bfloat162float(h);
            int idx = i * DIN + (j - 1);
            g_data_h[idx] = h;
            g_data_l[idx] = __float2bfloat16(lo);
        }
    }
}

// transpose + split all four weight matrices W[K,N] -> [N,K] bf16 hi/lo
__global__ void k_wt_all(const float* __restrict__ W1, const float* __restrict__ W2,
                         const float* __restrict__ W3, const float* __restrict__ W4) {
    const int S1 = DIN * HID, S2 = HID * EMBD, S3 = EMBD * HID, S4 = HID * DIN;
    const int T1 = S1, T2 = T1 + S2, T3 = T2 + S3, T4 = T3 + S4;
    for (int e = blockIdx.x * blockDim.x + threadIdx.x; e < T4;
         e += gridDim.x * blockDim.x) {
        const float* W;
        __nv_bfloat16 *th, *tl;
        int le, K, N;
        if (e < T1)      { W = W1; th = g_w1_h; tl = g_w1_l; le = e;      K = DIN;  N = HID;  }
        else if (e < T2) { W = W2; th = g_w2_h; tl = g_w2_l; le = e - T1; K = HID;  N = EMBD; }
        else if (e < T3) { W = W3; th = g_w3_h; tl = g_w3_l; le = e - T2; K = EMBD; N = HID;  }
        else             { W = W4; th = g_w4_h; tl = g_w4_l; le = e - T3; K = HID;  N = DIN;  }
        int k = le / N, n = le - k * N;
        float v = W[le];
        __nv_bfloat16 h = __float2bfloat16(v);
        float lo = v - __bfloat162float(h);
        th[n * K + k] = h;
        tl[n * K + k] = __float2bfloat16(lo);
    }
}

__global__ void k_offsets() {
    if (threadIdx.x == 0) {
        int s = 0;
        for (int c = 0; c < NCLS; c++) { g_off[c] = s; g_cur[c] = s; s += g_counts[c]; }
    }
}

__global__ void k_scatter() {
    int i = blockIdx.x * blockDim.x + threadIdx.x;
    if (i < NROWS) {
        int c = g_lbl[i];
        int p = atomicAdd(&g_cur[c], 1);
        g_idx[p] = i;
    }
}

// ======================= mma.sync bf16-split GEMM ===============================
template<int MT, int NT, int WR, int WC, int MINB>
__global__ __launch_bounds__(256, MINB)
void k_gemm_mma(const __nv_bfloat16* __restrict__ Ah, const __nv_bfloat16* __restrict__ Al,
                const __nv_bfloat16* __restrict__ Bh, const __nv_bfloat16* __restrict__ Bl,
                const float* __restrict__ bias, float* __restrict__ f32out,
                __nv_bfloat16* __restrict__ oh, __nv_bfloat16* __restrict__ ol,
                int K, int N, int act) {
    constexpr int MI   = MT / (WR * 16);
    constexpr int WN   = NT / WC;
    constexpr int NW8  = WN / 8;
    constexpr int NJ   = WN / 16;
    constexpr int MW   = MT / WR;
    constexpr int STRB = 80;
    constexpr int ABY  = MT * STRB;
    constexpr int BBY  = NT * STRB;
    constexpr int OFF_AL = ABY;
    constexpr int OFF_BH = 2 * ABY;
    constexpr int OFF_BL = 2 * ABY + BBY;
    constexpr int BUFSZ  = 2 * ABY + 2 * BBY;

    extern __shared__ __align__(16) char smem[];
    const uint32_t sbase = smem_u32(smem);

    const int tid = threadIdx.x;
    const int wid = tid >> 5, lane = tid & 31;
    const int wr = wid / WC, wc = wid % WC;
    const int bm = blockIdx.y * MT, bn = blockIdx.x * NT;

    float acc[MI][NW8][4];
#pragma unroll
    for (int a = 0; a < MI; a++)
#pragma unroll
        for (int b = 0; b < NW8; b++)
#pragma unroll
            for (int c = 0; c < 4; c++) acc[a][b][c] = 0.f;

    const int nch = K >> 5;

    auto load_chunk = [&](int buf, int kc) {
        const int k0 = kc << 5;
        const uint32_t sb = sbase + buf * BUFSZ;
        for (int u = tid; u < MT * 4; u += 256) {
            int r = u >> 2, s = u & 3;
            size_t go = (size_t)(bm + r) * K + k0 + s * 8;
            uint32_t so = (uint32_t)(r * STRB + s * 16);
            ld16(sb + so, Ah + go);
            ld16(sb + OFF_AL + so, Al + go);
        }
        for (int u = tid; u < NT * 4; u += 256) {
            int r = u >> 2, s = u & 3;
            size_t go = (size_t)(bn + r) * K + k0 + s * 8;
            uint32_t so = (uint32_t)(r * STRB + s * 16);
            ld16(sb + OFF_BH + so, Bh + go);
            ld16(sb + OFF_BL + so, Bl + go);
        }
        asm volatile("cp.async.commit_group;" ::: "memory");
    };

    load_chunk(0, 0);
    for (int kc = 0; kc < nch; kc++) {
        if (kc + 1 < nch) {
            load_chunk((kc + 1) & 1, kc + 1);
            asm volatile("cp.async.wait_group 1;" ::: "memory");
        } else {
            asm volatile("cp.async.wait_group 0;" ::: "memory");
        }
        __syncthreads();

        const uint32_t sb = sbase + (kc & 1) * BUFSZ;
#pragma unroll
        for (int ks = 0; ks < 2; ks++) {
            uint32_t ah[MI][4], alr[MI][4];
#pragma unroll
            for (int mi = 0; mi < MI; mi++) {
                uint32_t ar = wr * MW + mi * 16 + (lane & 15);
                uint32_t ac = ks * 16 + (lane >> 4) * 8;
                uint32_t ad = sb + ar * STRB + ac * 2;
                ldsm4(ah[mi], ad);
                ldsm4(alr[mi], ad + OFF_AL);
            }
            uint32_t br = wc * WN + ((lane >> 4) << 3) + (lane & 7);
            uint32_t bc = ks * 16 + ((lane >> 3) & 1) * 8;
#pragma unroll
            for (int nj = 0; nj < NJ; nj++) {
                uint32_t bd = sb + OFF_BH + (br + nj * 16) * STRB + bc * 2;
                uint32_t t[4], u4[4];
                ldsm4(t, bd);
                ldsm4(u4, bd + (OFF_BL - OFF_BH));
#pragma unroll
                for (int mi = 0; mi < MI; mi++) {
                    mma16816(acc[mi][2 * nj],     ah[mi], t);
                    mma16816(acc[mi][2 * nj + 1], ah[mi], t + 2);
                }
#pragma unroll
                for (int mi = 0; mi < MI; mi++) {
                    mma16816(acc[mi][2 * nj],     ah[mi], u4);
                    mma16816(acc[mi][2 * nj + 1], ah[mi], u4 + 2);
                }
#pragma unroll
                for (int mi = 0; mi < MI; mi++) {
                    mma16816(acc[mi][2 * nj],     alr[mi], t);
                    mma16816(acc[mi][2 * nj + 1], alr[mi], t + 2);
                }
            }
        }
        __syncthreads();
    }

    const int g = lane >> 2, i2 = (lane & 3) * 2;
#pragma unroll
    for (int mi = 0; mi < MI; mi++) {
#pragma unroll
        for (int ni = 0; ni < NW8; ni++) {
            int col = bn + wc * WN + ni * 8 + i2;
            float b0 = bias[col], b1 = bias[col + 1];
#pragma unroll
            for (int h = 0; h < 2; h++) {
                int row = bm + wr * MW + mi * 16 + g + h * 8;
                float v0 = acc[mi][ni][2 * h] + b0;
                float v1 = acc[mi][ni][2 * h + 1] + b1;
                if (act) { v0 = tanhf(v0); v1 = tanhf(v1); }
                size_t oi = (size_t)row * N + col;
                if (f32out) *(float2*)(f32out + oi) = make_float2(v0, v1);
                if (oh) {
                    __nv_bfloat16 h0 = __float2bfloat16(v0);
                    __nv_bfloat16 h1 = __float2bfloat16(v1);
                    float l0 = v0 - __bfloat162float(h0);
                    float l1 = v1 - __bfloat162float(h1);
                    *(__nv_bfloat162*)(oh + oi) = __halves2bfloat162(h0, h1);
                    *(__nv_bfloat162*)(ol + oi) =
                        __halves2bfloat162(__float2bfloat16(l0), __float2bfloat16(l1));
                }
            }
        }
    }
}

// ======================= fused per-class stats: sq, Q, S ========================
__global__ __launch_bounds__(256)
void k_stats() {
    __shared__ double sS[8][64];
    __shared__ double sQ[8];
    const int c = blockIdx.x;
    const int n = g_counts[c], off = g_off[c];
    const int w = threadIdx.x >> 5, lane = threadIdx.x & 31;

    double s0 = 0.0, s1 = 0.0, q = 0.0;
    for (int r = w; r < n; r += 8) {
        int row = g_idx[off + r];
        const float* e = g_emb + row * EMBD + 2;
        float v0 = e[lane];
        float v1 = (lane < NCON - 32) ? e[lane + 32] : 0.f;
        s0 += (double)v0;
        s1 += (double)v1;
        float sq = v0 * v0 + v1 * v1;
#pragma unroll
        for (int o = 16; o; o >>= 1) sq += __shfl_xor_sync(0xffffffff, sq, o);
        if (lane == 0) { g_sq[row] = sq; q += (double)sq; }
    }
    sS[w][lane] = s0;
    sS[w][lane + 32] = s1;
    if (lane == 0) sQ[w] = q;
    __syncthreads();
    int d = threadIdx.x;
    if (d < NCON) {
        double s = 0.0;
        for (int k = 0; k < 8; k++) s += sS[k][d];
        g_S[c * NCON + d] = s;
    }
    if (d == 64) {
        double s = 0.0;
        for (int k = 0; k < 8; k++) s += sQ[k];
        g_Q[c] = s;
    }
}

// ======================= same-class pairwise hinge (triangular) =================
__global__ __launch_bounds__(256)
void k_pairs() {
    const int c   = blockIdx.y;
    const int n   = g_counts[c];
    const int off = g_off[c];
    const int nt  = (n + 63) >> 6;
    const int tot = nt * (nt + 1) / 2;

    __shared__ float  smA[NCON][68];
    __shared__ float  smB[NCON][68];
    __shared__ float  sqA[64], sqB[64];
    __shared__ double red[256];

    const int tid = threadIdx.x;
    const int ty  = tid >> 4, tx = tid & 15;
    double acc = 0.0;

    for (int t = blockIdx.x; t < tot; t += gridDim.x) {
        int rem = t, TI = 0;
        while (rem >= nt - TI) { rem -= nt - TI; TI++; }
        int TJ = TI + rem;
        float w = (TI == TJ) ? 1.0f : 2.0f;
        int i0 = TI * 64, j0 = TJ * 64;
        __syncthreads();
        for (int e = tid; e < 64 * 64; e += 256) {
            int r = e >> 6, d = e & 63;
            if (d < NCON) {
                int ri = i0 + r, rj = j0 + r;
                smA[d][r] = (ri < n) ? g_emb[g_idx[off + ri] * EMBD + 2 + d] : 0.f;
                smB[d][r] = (rj < n) ? g_emb[g_idx[off + rj] * EMBD + 2 + d] : 0.f;
            }
        }
        if (tid < 64) {
            sqA[tid] = (i0 + tid < n) ? g_sq[g_idx[off + i0 + tid]] : 1e30f;
            sqB[tid] = (j0 + tid < n) ? g_sq[g_idx[off + j0 + tid]] : 1e30f;
        }
        __syncthreads();
        float dot[4][4] = {};
#pragma unroll
        for (int k = 0; k < NCON; k++) {
            float a[4], b[4];
#pragma unroll
            for (int i = 0; i < 4; i++) a[i] = smA[k][ty * 4 + i];
#pragma unroll
            for (int j = 0; j < 4; j++) b[j] = smB[k][tx * 4 + j];
#pragma unroll
            for (int i = 0; i < 4; i++)
#pragma unroll
                for (int j = 0; j < 4; j++) dot[i][j] += a[i] * b[j];
        }
        float ts = 0.f;
#pragma unroll
        for (int i = 0; i < 4; i++) {
            float si = sqA[ty * 4 + i];
#pragma unroll
            for (int j = 0; j < 4; j++) {
                float df = si + sqB[tx * 4 + j] - 2.f * dot[i][j];
                float dm = fmaxf(df, 0.f) * (1.0f / 62.0f);
                ts += fmaxf(0.f, MARGINF - dm);
            }
        }
        acc += (double)(w * ts);
    }
    red[tid] = acc;
    __syncthreads();
    for (int o = 128; o; o >>= 1) {
        if (tid < o) red[tid] += red[tid + o];
        __syncthreads();
    }
    if (tid == 0 && red[0] != 0.0) atomicAdd(&g_cdiff, red[0]);
}

// ======================= finalize scalars =======================================
__global__ void k_final(float* __restrict__ out) {
    __shared__ double shA[64], shB[64];
    int d = threadIdx.x;
    double sgd = 0.0, s2c = 0.0;
    if (d < NCON) {
        for (int c = 0; c < NCLS; c++) {
            double v = g_S[c * NCON + d];
            sgd += v;
            s2c += v * v;
        }
    }
    shA[d] = sgd * sgd;
    shB[d] = s2c;
    __syncthreads();
    if (d == 0) {
        double S2g = 0.0, S2c = 0.0;
        for (int k = 0; k < 64; k++) { S2g += shA[k]; S2c += shB[k]; }
        double T = 0.0, sumn2 = 0.0, snq = 0.0;
        for (int c = 0; c < NCLS; c++) {
            double nc = (double)g_counts[c];
            T     += g_Q[c];
            sumn2 += nc * nc;
            snq   += 2.0 * nc * g_Q[c];
        }
        double Nd     = (double)NROWS;
        double n_diff = Nd * Nd - sumn2;
        double sum_all  = 2.0 * Nd * T - 2.0 * S2g;
        double sum_same = snq - 2.0 * S2c;
        double C_sim  = (sum_all - sum_same) / 62.0 / (n_diff + 1.0);
        double C_diff = g_cdiff / (Nd * Nd - n_diff + 1.0);
        out[OUT_OFF + 0] = (float)C_sim;
        out[OUT_OFF + 1] = (float)C_diff;
    }
}

// ======================= launch =================================================
extern "C" void kernel_launch(void* const* d_in, const int* in_sizes, int n_in,
                              void* d_out, int out_size) {
    const float* x  = (const float*)d_in[0];
    const float* W1 = (const float*)d_in[1];
    const float* b1 = (const float*)d_in[2];
    const float* W2 = (const float*)d_in[3];
    const float* b2 = (const float*)d_in[4];
    const float* W3 = (const float*)d_in[5];
    const float* b3 = (const float*)d_in[6];
    const float* W4 = (const float*)d_in[7];
    const float* b4 = (const float*)d_in[8];
    float* out = (float*)d_out;

    // L1/L4: 128x64 tile, 4x2 warps, 3 CTAs/SM -> 61440B dyn smem
    cudaFuncSetAttribute((const void*)k_gemm_mma<128, 64, 4, 2, 3>,
                         cudaFuncAttributeMaxDynamicSharedMemorySize, 61440);
    // L3: 64x64 tile, 4x2 warps, 4 CTAs/SM -> 40960B dyn smem
    cudaFuncSetAttribute((const void*)k_gemm_mma<64, 64, 4, 2, 4>,
                         cudaFuncAttributeMaxDynamicSharedMemorySize, 40960);
    // L2: 64x32 tile, 4x2 warps, 4 CTAs/SM -> 30720B dyn smem
    cudaFuncSetAttribute((const void*)k_gemm_mma<64, 32, 4, 2, 4>,
                         cudaFuncAttributeMaxDynamicSharedMemorySize, 30720);

    __nv_bfloat16 *dh, *dl, *h1h, *h1l, *eh, *el, *h2h, *h2l;
    __nv_bfloat16 *w1h, *w1l, *w2h, *w2l, *w3h, *w3l, *w4h, *w4l;
    float* pemb;
    cudaGetSymbolAddress((void**)&dh,  g_data_h); cudaGetSymbolAddress((void**)&dl,  g_data_l);
    cudaGetSymbolAddress((void**)&h1h, g_h1_h);   cudaGetSymbolAddress((void**)&h1l, g_h1_l);
    cudaGetSymbolAddress((void**)&eh,  g_emb_h);  cudaGetSymbolAddress((void**)&el,  g_emb_l);
    cudaGetSymbolAddress((void**)&h2h, g_h2_h);   cudaGetSymbolAddress((void**)&h2l, g_h2_l);
    cudaGetSymbolAddress((void**)&w1h, g_w1_h);   cudaGetSymbolAddress((void**)&w1l, g_w1_l);
    cudaGetSymbolAddress((void**)&w2h, g_w2_h);   cudaGetSymbolAddress((void**)&w2l, g_w2_l);
    cudaGetSymbolAddress((void**)&w3h, g_w3_h);   cudaGetSymbolAddress((void**)&w3l, g_w3_l);
    cudaGetSymbolAddress((void**)&w4h, g_w4_h);   cudaGetSymbolAddress((void**)&w4l, g_w4_l);
    cudaGetSymbolAddress((void**)&pemb, g_emb);

    k_init<<<1, 1024>>>();                                   // my #0
    k_prep<<<4096, 256>>>(x);                                // my #1
    k_wt_all<<<2304, 256>>>(W1, W2, W3, W4);                 // my #2

    // L1: h1 = tanh(data @ W1 + b1)  [8192,1024], K=512 --- my #3 (ncu target)
    k_gemm_mma<128, 64, 4, 2, 3><<<dim3(HID / 64, NROWS / 128), 256, 61440>>>(
        dh, dl, w1h, w1l, b1, nullptr, h1h, h1l, DIN, HID, 1);

    k_offsets<<<1, 32>>>();
    k_scatter<<<32, 256>>>();

    // L2: emb = h1 @ W2 + b2         [8192,64], K=1024
    k_gemm_mma<64, 32, 4, 2, 4><<<dim3(EMBD / 32, NROWS / 64), 256, 30720>>>(
        h1h, h1l, w2h, w2l, b2, pemb, eh, el, HID, EMBD, 0);
    k_stats<<<NCLS, 256>>>();
    // L3: h2 = tanh(emb @ W3 + b3)   [8192,1024], K=64
    k_gemm_mma<64, 64, 4, 2, 4><<<dim3(HID / 64, NROWS / 64), 256, 40960>>>(
        eh, el, w3h, w3l, b3, nullptr, h2h, h2l, EMBD, HID, 1);
    // L4: decoded = h2 @ W4 + b4 -> d_out  [8192,512], K=1024
    k_gemm_mma<128, 64, 4, 2, 3><<<dim3(DIN / 64, NROWS / 128), 256, 61440>>>(
        h2h, h2l, w4h, w4l, b4, out, nullptr, nullptr, HID, DIN, 0);

    k_pairs<<<dim3(40, NCLS), 256>>>();
    k_final<<<1, 64>>>(out);
}

// round 10
// speedup vs baseline: 2.2469x; 1.0019x over previous
#include <cuda_runtime.h>
#include <cuda_bf16.h>
#include <cstdint>
#include <math.h>

#define NROWS 8192
#define DIN   512
#define HID   1024
#define EMBD  64
#define NCON  62
#define NCLS  16
#define MARGINF 0.01f
#define OUT_OFF (NROWS * DIN)

// ======================= helpers ================================================
__device__ __forceinline__ void ld16(uint32_t s, const void* g) {
    asm volatile("cp.async.cg.shared.global [%0], [%1], 16;" :: "r"(s), "l"(g));
}
__device__ __forceinline__ uint32_t smem_u32(const void* p) {
    uint32_t a;
    asm("{ .reg .u64 t; cvta.to.shared.u64 t, %1; cvt.u32.u64 %0, t; }" : "=r"(a) : "l"(p));
    return a;
}
__device__ __forceinline__ void ldsm4(uint32_t* r, uint32_t addr) {
    asm volatile("ldmatrix.sync.aligned.m8n8.x4.shared.b16 {%0,%1,%2,%3}, [%4];"
        : "=r"(r[0]), "=r"(r[1]), "=r"(r[2]), "=r"(r[3]) : "r"(addr));
}
__device__ __forceinline__ void mma16816(float* c, const uint32_t* a, const uint32_t* b) {
    asm volatile("mma.sync.aligned.m16n8k16.row.col.f32.bf16.bf16.f32 "
        "{%0,%1,%2,%3}, {%4,%5,%6,%7}, {%8,%9}, {%0,%1,%2,%3};"
        : "+f"(c[0]), "+f"(c[1]), "+f"(c[2]), "+f"(c[3])
        : "r"(a[0]), "r"(a[1]), "r"(a[2]), "r"(a[3]), "r"(b[0]), "r"(b[1]));
}

// ======================= scratch (device globals) ===============================
__device__ __nv_bfloat16 g_data_h[NROWS * DIN],  g_data_l[NROWS * DIN];
__device__ __nv_bfloat16 g_h1_h[NROWS * HID],    g_h1_l[NROWS * HID];
__device__ __nv_bfloat16 g_emb_h[NROWS * EMBD],  g_emb_l[NROWS * EMBD];
__device__ __nv_bfloat16 g_h2_h[NROWS * HID],    g_h2_l[NROWS * HID];
__device__ __nv_bfloat16 g_w1_h[HID * DIN],  g_w1_l[HID * DIN];    // [N,K]
__device__ __nv_bfloat16 g_w2_h[EMBD * HID], g_w2_l[EMBD * HID];
__device__ __nv_bfloat16 g_w3_h[HID * EMBD], g_w3_l[HID * EMBD];
__device__ __nv_bfloat16 g_w4_h[DIN * HID],  g_w4_l[DIN * HID];
__device__ float  g_emb[NROWS * EMBD];
__device__ int    g_lbl[NROWS];
__device__ float  g_sq[NROWS];
__device__ int    g_counts[NCLS], g_off[NCLS], g_cur[NCLS], g_idx[NROWS];
__device__ double g_S[NCLS * NCON];
__device__ double g_Q[NCLS];
__device__ double g_cdiff;
__device__ int    g_ctr[8];   // per-layer persistent tile counters

// ======================= small kernels ==========================================
__global__ void k_init() {
    int t = threadIdx.x;
    if (t < NCLS) { g_counts[t] = 0; g_Q[t] = 0.0; }
    if (t < 8) g_ctr[t] = 0;
    if (t == 0) g_cdiff = 0.0;
    for (int i = t; i < NCLS * NCON; i += blockDim.x) g_S[i] = 0.0;
}

__global__ void k_prep(const float* __restrict__ x) {
    const int total = NROWS * (DIN + 1);
    for (int e = blockIdx.x * blockDim.x + threadIdx.x; e < total;
         e += gridDim.x * blockDim.x) {
        int i = e / (DIN + 1);
        int j = e - i * (DIN + 1);
        float v = x[e];
        if (j == 0) {
            int c = (int)v;
            g_lbl[i] = c;
            atomicAdd(&g_counts[c], 1);
        } else {
            __nv_bfloat16 h = __float2bfloat16(v);
            float lo = v - __bfloat162float(h);
            int idx = i * DIN + (j - 1);
            g_data_h[idx] = h;
            g_data_l[idx] = __float2bfloat16(lo);
        }
    }
}

// transpose + split all four weight matrices W[K,N] -> [N,K] bf16 hi/lo
__global__ void k_wt_all(const float* __restrict__ W1, const float* __restrict__ W2,
                         const float* __restrict__ W3, const float* __restrict__ W4) {
    const int S1 = DIN * HID, S2 = HID * EMBD, S3 = EMBD * HID, S4 = HID * DIN;
    const int T1 = S1, T2 = T1 + S2, T3 = T2 + S3, T4 = T3 + S4;
    for (int e = blockIdx.x * blockDim.x + threadIdx.x; e < T4;
         e += gridDim.x * blockDim.x) {
        const float* W;
        __nv_bfloat16 *th, *tl;
        int le, K, N;
        if (e < T1)      { W = W1; th = g_w1_h; tl = g_w1_l; le = e;      K = DIN;  N = HID;  }
        else if (e < T2) { W = W2; th = g_w2_h; tl = g_w2_l; le = e - T1; K = HID;  N = EMBD; }
        else if (e < T3) { W = W3; th = g_w3_h; tl = g_w3_l; le = e - T2; K = EMBD; N = HID;  }
        else             { W = W4; th = g_w4_h; tl = g_w4_l; le = e - T3; K = HID;  N = DIN;  }
        int k = le / N, n = le - k * N;
        float v = W[le];
        __nv_bfloat16 h = __float2bfloat16(v);
        float lo = v - __bfloat162float(h);
        th[n * K + k] = h;
        tl[n * K + k] = __float2bfloat16(lo);
    }
}

__global__ void k_offsets() {
    if (threadIdx.x == 0) {
        int s = 0;
        for (int c = 0; c < NCLS; c++) { g_off[c] = s; g_cur[c] = s; s += g_counts[c]; }
    }
}

__global__ void k_scatter() {
    int i = blockIdx.x * blockDim.x + threadIdx.x;
    if (i < NROWS) {
        int c = g_lbl[i];
        int p = atomicAdd(&g_cur[c], 1);
        g_idx[p] = i;
    }
}

// ======================= persistent mma.sync bf16-split GEMM ====================
// Tiles popped from g_ctr[layer]; continuous cross-tile chunk stream keeps the
// NS-stage cp.async pipeline full across tile boundaries.
template<int MT, int NT, int WR, int WC, int MINB, int NS>
__global__ __launch_bounds__(256, MINB)
void k_gemm_mma(const __nv_bfloat16* __restrict__ Ah, const __nv_bfloat16* __restrict__ Al,
                const __nv_bfloat16* __restrict__ Bh, const __nv_bfloat16* __restrict__ Bl,
                const float* __restrict__ bias, float* __restrict__ f32out,
                __nv_bfloat16* __restrict__ oh, __nv_bfloat16* __restrict__ ol,
                int K, int N, int act, int lgx, int ntiles, int layer) {
    constexpr int MI   = MT / (WR * 16);
    constexpr int WN   = NT / WC;
    constexpr int NW8  = WN / 8;
    constexpr int NJ   = WN / 16;
    constexpr int MW   = MT / WR;
    constexpr int STRB = 80;
    constexpr int ABY  = MT * STRB;
    constexpr int BBY  = NT * STRB;
    constexpr int OFF_AL = ABY;
    constexpr int OFF_BH = 2 * ABY;
    constexpr int OFF_BL = 2 * ABY + BBY;
    constexpr int BUFSZ  = 2 * ABY + 2 * BBY;

    extern __shared__ __align__(16) char smem[];
    const uint32_t sbase = smem_u32(smem);
    __shared__ int sh_tile;

    const int tid = threadIdx.x;
    const int wid = tid >> 5, lane = tid & 31;
    const int wr = wid / WC, wc = wid % WC;
    const int gxm = (1 << lgx) - 1;
    const int nch = K >> 5;

    if (tid == 0) sh_tile = atomicAdd(&g_ctr[layer], 1);
    __syncthreads();
    int cur = sh_tile;
    if (cur >= ntiles) return;

    auto load_chunk = [&](int ti, int kc, int buf) {
        const int bm = (ti >> lgx) * MT;
        const int bn = (ti & gxm) * NT;
        const int k0 = kc << 5;
        const uint32_t sb = sbase + buf * BUFSZ;
        for (int u = tid; u < MT * 4; u += 256) {
            int r = u >> 2, s = u & 3;
            size_t go = (size_t)(bm + r) * K + k0 + s * 8;
            uint32_t so = (uint32_t)(r * STRB + s * 16);
            ld16(sb + so, Ah + go);
            ld16(sb + OFF_AL + so, Al + go);
        }
        for (int u = tid; u < NT * 4; u += 256) {
            int r = u >> 2, s = u & 3;
            size_t go = (size_t)(bn + r) * K + k0 + s * 8;
            uint32_t so = (uint32_t)(r * STRB + s * 16);
            ld16(sb + OFF_BH + so, Bh + go);
            ld16(sb + OFF_BL + so, Bl + go);
        }
        asm volatile("cp.async.commit_group;" ::: "memory");
    };

    // prologue: NS-1 chunks of the first tile (requires nch >= NS-1)
#pragma unroll
    for (int p = 0; p < NS - 1; p++) load_chunk(cur, p, p);

    int pos = 0;
    while (true) {
        float acc[MI][NW8][4];
#pragma unroll
        for (int a = 0; a < MI; a++)
#pragma unroll
            for (int b = 0; b < NW8; b++)
#pragma unroll
                for (int c = 0; c < 4; c++) acc[a][b][c] = 0.f;

        int nxt = ntiles;
        for (int kc = 0; kc < nch; kc++) {
            const int lk = kc + NS - 1;
            const int lbuf = (pos + NS - 1) & (NS - 1);
            if (lk < nch) {
                load_chunk(cur, lk, lbuf);
            } else {
                if (lk == nch) {
                    if (tid == 0) sh_tile = atomicAdd(&g_ctr[layer], 1);
                    __syncthreads();
                    nxt = sh_tile;
                }
                if (nxt < ntiles) load_chunk(nxt, lk - nch, lbuf);
                else asm volatile("cp.async.commit_group;" ::: "memory");
            }
            asm volatile("cp.async.wait_group %0;" :: "n"(NS - 1));
            __syncthreads();

            const uint32_t sb = sbase + (pos & (NS - 1)) * BUFSZ;
#pragma unroll
            for (int ks = 0; ks < 2; ks++) {
                uint32_t ah[MI][4], alr[MI][4];
#pragma unroll
                for (int mi = 0; mi < MI; mi++) {
                    uint32_t ar = wr * MW + mi * 16 + (lane & 15);
                    uint32_t ac = ks * 16 + (lane >> 4) * 8;
                    uint32_t ad = sb + ar * STRB + ac * 2;
                    ldsm4(ah[mi], ad);
                    ldsm4(alr[mi], ad + OFF_AL);
                }
                uint32_t br = wc * WN + ((lane >> 4) << 3) + (lane & 7);
                uint32_t bc = ks * 16 + ((lane >> 3) & 1) * 8;
#pragma unroll
                for (int nj = 0; nj < NJ; nj++) {
                    uint32_t bd = sb + OFF_BH + (br + nj * 16) * STRB + bc * 2;
                    uint32_t t[4], u4[4];
                    ldsm4(t, bd);
                    ldsm4(u4, bd + (OFF_BL - OFF_BH));
#pragma unroll
                    for (int mi = 0; mi < MI; mi++) {
                        mma16816(acc[mi][2 * nj],     ah[mi], t);
                        mma16816(acc[mi][2 * nj + 1], ah[mi], t + 2);
                    }
#pragma unroll
                    for (int mi = 0; mi < MI; mi++) {
                        mma16816(acc[mi][2 * nj],     ah[mi], u4);
                        mma16816(acc[mi][2 * nj + 1], ah[mi], u4 + 2);
                    }
#pragma unroll
                    for (int mi = 0; mi < MI; mi++) {
                        mma16816(acc[mi][2 * nj],     alr[mi], t);
                        mma16816(acc[mi][2 * nj + 1], alr[mi], t + 2);
                    }
                }
            }
            __syncthreads();
            pos++;
        }

        // epilogue for cur (register -> global, no smem: overlaps next-tile loads)
        {
            const int bm = (cur >> lgx) * MT;
            const int bn = (cur & gxm) * NT;
            const int g = lane >> 2, i2 = (lane & 3) * 2;
#pragma unroll
            for (int mi = 0; mi < MI; mi++) {
#pragma unroll
                for (int ni = 0; ni < NW8; ni++) {
                    int col = bn + wc * WN + ni * 8 + i2;
                    float b0 = bias[col], b1 = bias[col + 1];
#pragma unroll
                    for (int h = 0; h < 2; h++) {
                        int row = bm + wr * MW + mi * 16 + g + h * 8;
                        float v0 = acc[mi][ni][2 * h] + b0;
                        float v1 = acc[mi][ni][2 * h + 1] + b1;
                        if (act) { v0 = tanhf(v0); v1 = tanhf(v1); }
                        size_t oi = (size_t)row * N + col;
                        if (f32out) *(float2*)(f32out + oi) = make_float2(v0, v1);
                        if (oh) {
                            __nv_bfloat16 h0 = __float2bfloat16(v0);
                            __nv_bfloat16 h1 = __float2bfloat16(v1);
                            float l0 = v0 - __bfloat162float(h0);
                            float l1 = v1 - __bfloat162float(h1);
                            *(__nv_bfloat162*)(oh + oi) = __halves2bfloat162(h0, h1);
                            *(__nv_bfloat162*)(ol + oi) =
                                __halves2bfloat162(__float2bfloat16(l0), __float2bfloat16(l1));
                        }
                    }
                }
            }
        }
        if (nxt >= ntiles) return;
        cur = nxt;
    }
}

// ======================= fused per-class stats: sq, Q, S ========================
__global__ __launch_bounds__(256)
void k_stats() {
    __shared__ double sS[8][64];
    __shared__ double sQ[8];
    const int c = blockIdx.x;
    const int n = g_counts[c], off = g_off[c];
    const int w = threadIdx.x >> 5, lane = threadIdx.x & 31;

    double s0 = 0.0, s1 = 0.0, q = 0.0;
    for (int r = w; r < n; r += 8) {
        int row = g_idx[off + r];
        const float* e = g_emb + row * EMBD + 2;
        float v0 = e[lane];
        float v1 = (lane < NCON - 32) ? e[lane + 32] : 0.f;
        s0 += (double)v0;
        s1 += (double)v1;
        float sq = v0 * v0 + v1 * v1;
#pragma unroll
        for (int o = 16; o; o >>= 1) sq += __shfl_xor_sync(0xffffffff, sq, o);
        if (lane == 0) { g_sq[row] = sq; q += (double)sq; }
    }
    sS[w][lane] = s0;
    sS[w][lane + 32] = s1;
    if (lane == 0) sQ[w] = q;
    __syncthreads();
    int d = threadIdx.x;
    if (d < NCON) {
        double s = 0.0;
        for (int k = 0; k < 8; k++) s += sS[k][d];
        g_S[c * NCON + d] = s;
    }
    if (d == 64) {
        double s = 0.0;
        for (int k = 0; k < 8; k++) s += sQ[k];
        g_Q[c] = s;
    }
}

// ======================= same-class pairwise hinge (triangular) =================
__global__ __launch_bounds__(256)
void k_pairs() {
    const int c   = blockIdx.y;
    const int n   = g_counts[c];
    const int off = g_off[c];
    const int nt  = (n + 63) >> 6;
    const int tot = nt * (nt + 1) / 2;

    __shared__ float  smA[NCON][68];
    __shared__ float  smB[NCON][68];
    __shared__ float  sqA[64], sqB[64];
    __shared__ double red[256];

    const int tid = threadIdx.x;
    const int ty  = tid >> 4, tx = tid & 15;
    double acc = 0.0;

    for (int t = blockIdx.x; t < tot; t += gridDim.x) {
        int rem = t, TI = 0;
        while (rem >= nt - TI) { rem -= nt - TI; TI++; }
        int TJ = TI + rem;
        float w = (TI == TJ) ? 1.0f : 2.0f;
        int i0 = TI * 64, j0 = TJ * 64;
        __syncthreads();
        for (int e = tid; e < 64 * 64; e += 256) {
            int r = e >> 6, d = e & 63;
            if (d < NCON) {
                int ri = i0 + r, rj = j0 + r;
                smA[d][r] = (ri < n) ? g_emb[g_idx[off + ri] * EMBD + 2 + d] : 0.f;
                smB[d][r] = (rj < n) ? g_emb[g_idx[off + rj] * EMBD + 2 + d] : 0.f;
            }
        }
        if (tid < 64) {
            sqA[tid] = (i0 + tid < n) ? g_sq[g_idx[off + i0 + tid]] : 1e30f;
            sqB[tid] = (j0 + tid < n) ? g_sq[g_idx[off + j0 + tid]] : 1e30f;
        }
        __syncthreads();
        float dot[4][4] = {};
#pragma unroll
        for (int k = 0; k < NCON; k++) {
            float a[4], b[4];
#pragma unroll
            for (int i = 0; i < 4; i++) a[i] = smA[k][ty * 4 + i];
#pragma unroll
            for (int j = 0; j < 4; j++) b[j] = smB[k][tx * 4 + j];
#pragma unroll
            for (int i = 0; i < 4; i++)
#pragma unroll
                for (int j = 0; j < 4; j++) dot[i][j] += a[i] * b[j];
        }
        float ts = 0.f;
#pragma unroll
        for (int i = 0; i < 4; i++) {
            float si = sqA[ty * 4 + i];
#pragma unroll
            for (int j = 0; j < 4; j++) {
                float df = si + sqB[tx * 4 + j] - 2.f * dot[i][j];
                float dm = fmaxf(df, 0.f) * (1.0f / 62.0f);
                ts += fmaxf(0.f, MARGINF - dm);
            }
        }
        acc += (double)(w * ts);
    }
    red[tid] = acc;
    __syncthreads();
    for (int o = 128; o; o >>= 1) {
        if (tid < o) red[tid] += red[tid + o];
        __syncthreads();
    }
    if (tid == 0 && red[0] != 0.0) atomicAdd(&g_cdiff, red[0]);
}

// ======================= finalize scalars =======================================
__global__ void k_final(float* __restrict__ out) {
    __shared__ double shA[64], shB[64];
    int d = threadIdx.x;
    double sgd = 0.0, s2c = 0.0;
    if (d < NCON) {
        for (int c = 0; c < NCLS; c++) {
            double v = g_S[c * NCON + d];
            sgd += v;
            s2c += v * v;
        }
    }
    shA[d] = sgd * sgd;
    shB[d] = s2c;
    __syncthreads();
    if (d == 0) {
        double S2g = 0.0, S2c = 0.0;
        for (int k = 0; k < 64; k++) { S2g += shA[k]; S2c += shB[k]; }
        double T = 0.0, sumn2 = 0.0, snq = 0.0;
        for (int c = 0; c < NCLS; c++) {
            double nc = (double)g_counts[c];
            T     += g_Q[c];
            sumn2 += nc * nc;
            snq   += 2.0 * nc * g_Q[c];
        }
        double Nd     = (double)NROWS;
        double n_diff = Nd * Nd - sumn2;
        double sum_all  = 2.0 * Nd * T - 2.0 * S2g;
        double sum_same = snq - 2.0 * S2c;
        double C_sim  = (sum_all - sum_same) / 62.0 / (n_diff + 1.0);
        double C_diff = g_cdiff / (Nd * Nd - n_diff + 1.0);
        out[OUT_OFF + 0] = (float)C_sim;
        out[OUT_OFF + 1] = (float)C_diff;
    }
}

// ======================= launch =================================================
extern "C" void kernel_launch(void* const* d_in, const int* in_sizes, int n_in,
                              void* d_out, int out_size) {
    const float* x  = (const float*)d_in[0];
    const float* W1 = (const float*)d_in[1];
    const float* b1 = (const float*)d_in[2];
    const float* W2 = (const float*)d_in[3];
    const float* b2 = (const float*)d_in[4];
    const float* W3 = (const float*)d_in[5];
    const float* b3 = (const float*)d_in[6];
    const float* W4 = (const float*)d_in[7];
    const float* b4 = (const float*)d_in[8];
    float* out = (float*)d_out;

    // L1/L4: 128x64 tile, 3 CTAs/SM, 2-stage -> 61440B
    cudaFuncSetAttribute((const void*)k_gemm_mma<128, 64, 4, 2, 3, 2>,
                         cudaFuncAttributeMaxDynamicSharedMemorySize, 61440);
    // L3: 64x64 tile, 4 CTAs/SM, 2-stage -> 40960B
    cudaFuncSetAttribute((const void*)k_gemm_mma<64, 64, 4, 2, 4, 2>,
                         cudaFuncAttributeMaxDynamicSharedMemorySize, 40960);
    // L2: 64x32 tile, 2 CTAs/SM, 4-stage -> 61440B
    cudaFuncSetAttribute((const void*)k_gemm_mma<64, 32, 4, 2, 2, 4>,
                         cudaFuncAttributeMaxDynamicSharedMemorySize, 61440);

    __nv_bfloat16 *dh, *dl, *h1h, *h1l, *eh, *el, *h2h, *h2l;
    __nv_bfloat16 *w1h, *w1l, *w2h, *w2l, *w3h, *w3l, *w4h, *w4l;
    float* pemb;
    cudaGetSymbolAddress((void**)&dh,  g_data_h); cudaGetSymbolAddress((void**)&dl,  g_data_l);
    cudaGetSymbolAddress((void**)&h1h, g_h1_h);   cudaGetSymbolAddress((void**)&h1l, g_h1_l);
    cudaGetSymbolAddress((void**)&eh,  g_emb_h);  cudaGetSymbolAddress((void**)&el,  g_emb_l);
    cudaGetSymbolAddress((void**)&h2h, g_h2_h);   cudaGetSymbolAddress((void**)&h2l, g_h2_l);
    cudaGetSymbolAddress((void**)&w1h, g_w1_h);   cudaGetSymbolAddress((void**)&w1l, g_w1_l);
    cudaGetSymbolAddress((void**)&w2h, g_w2_h);   cudaGetSymbolAddress((void**)&w2l, g_w2_l);
    cudaGetSymbolAddress((void**)&w3h, g_w3_h);   cudaGetSymbolAddress((void**)&w3l, g_w3_l);
    cudaGetSymbolAddress((void**)&w4h, g_w4_h);   cudaGetSymbolAddress((void**)&w4l, g_w4_l);
    cudaGetSymbolAddress((void**)&pemb, g_emb);

    k_init<<<1, 1024>>>();                                   // my #0
    k_prep<<<4096, 256>>>(x);                                // my #1
    k_wt_all<<<2304, 256>>>(W1, W2, W3, W4);                 // my #2

    // L1: h1 = tanh(data @ W1 + b1)  [8192,1024], K=512 --- my #3 (ncu target)
    // 1024 tiles (gx=16), persistent grid 456
    k_gemm_mma<128, 64, 4, 2, 3, 2><<<456, 256, 61440>>>(
        dh, dl, w1h, w1l, b1, nullptr, h1h, h1l, DIN, HID, 1, 4, 1024, 0);

    k_offsets<<<1, 32>>>();
    k_scatter<<<32, 256>>>();

    // L2: emb = h1 @ W2 + b2  [8192,64], K=1024 -- 256 tiles (gx=2), 4-stage
    k_gemm_mma<64, 32, 4, 2, 2, 4><<<304, 256, 61440>>>(
        h1h, h1l, w2h, w2l, b2, pemb, eh, el, HID, EMBD, 0, 1, 256, 1);
    k_stats<<<NCLS, 256>>>();
    // L3: h2 = tanh(emb @ W3 + b3)  [8192,1024], K=64 -- 2048 tiles (gx=16)
    k_gemm_mma<64, 64, 4, 2, 4, 2><<<608, 256, 40960>>>(
        eh, el, w3h, w3l, b3, nullptr, h2h, h2l, EMBD, HID, 1, 4, 2048, 2);
    // L4: decoded = h2 @ W4 + b4 -> d_out  [8192,512], K=1024 -- 512 tiles (gx=8)
    k_gemm_mma<128, 64, 4, 2, 3, 2><<<456, 256, 61440>>>(
        h2h, h2l, w4h, w4l, b4, out, nullptr, nullptr, HID, DIN, 0, 3, 512, 3);

    k_pairs<<<dim3(40, NCLS), 256>>>();
    k_final<<<1, 64>>>(out);
}